// round 9
// baseline (speedup 1.0000x reference)
#include <cuda_runtime.h>
#include <cuda_bf16.h>
#include <cstdint>
#include <math.h>

#define BDIM 32
#define SDIM 256
#define EDIM 768
#define HDIM 32
#define DDIM 24
#define ROWS (BDIM*SDIM)     /* 8192 */
#define QKVN (3*EDIM)        /* 2304 */

// ---------------- device scratch ----------------
__device__ __align__(16) __nv_bfloat16 g_a_hi[(size_t)ROWS * EDIM];
__device__ __align__(16) __nv_bfloat16 g_a_lo[(size_t)ROWS * EDIM];
__device__ __align__(16) __nv_bfloat16 g_b_hi[(size_t)QKVN * EDIM];   // wt[n][k]
__device__ __align__(16) __nv_bfloat16 g_b_lo[(size_t)QKVN * EDIM];
// q/k in attn-ready packed bf16 hi/lo: [b][h][s][32] (cols 24..31 stay zero)
__device__ __align__(16) __nv_bfloat16 g_qh[(size_t)ROWS * HDIM * 32];
__device__ __align__(16) __nv_bfloat16 g_ql[(size_t)ROWS * HDIM * 32];
__device__ __align__(16) __nv_bfloat16 g_kh[(size_t)ROWS * HDIM * 32];
__device__ __align__(16) __nv_bfloat16 g_kl[(size_t)ROWS * HDIM * 32];
__device__ float g_v [(size_t)ROWS * EDIM];
__device__ float g_vp[(size_t)ROWS * HDIM * 4];

// ---------------- PTX helpers (base sm_80+ ISA only) ----------------
__device__ __forceinline__ uint32_t smem_to_u32(const void* p) {
    uint32_t a;
    asm("{ .reg .u64 t; cvta.to.shared.u64 t, %1; cvt.u32.u64 %0, t; }" : "=r"(a) : "l"(p));
    return a;
}
__device__ __forceinline__ void cp_async16(uint32_t s, const void* g) {
    asm volatile("cp.async.cg.shared.global [%0], [%1], 16;" :: "r"(s), "l"(g) : "memory");
}
__device__ __forceinline__ void ldsm4(uint32_t* r, uint32_t addr) {
    asm volatile("ldmatrix.sync.aligned.m8n8.x4.shared.b16 {%0,%1,%2,%3}, [%4];"
                 : "=r"(r[0]), "=r"(r[1]), "=r"(r[2]), "=r"(r[3]) : "r"(addr));
}
__device__ __forceinline__ void mma16816(float* c, const uint32_t* a, const uint32_t* b) {
    asm volatile("mma.sync.aligned.m16n8k16.row.col.f32.bf16.bf16.f32 "
                 "{%0,%1,%2,%3}, {%4,%5,%6,%7}, {%8,%9}, {%0,%1,%2,%3};"
                 : "+f"(c[0]), "+f"(c[1]), "+f"(c[2]), "+f"(c[3])
                 : "r"(a[0]), "r"(a[1]), "r"(a[2]), "r"(a[3]), "r"(b[0]), "r"(b[1]));
}

// ---------------- prep: feats -> bf16 hi/lo ----------------
__global__ __launch_bounds__(256) void prep_a_kernel(const float* __restrict__ feats)
{
    const size_t i = (size_t)blockIdx.x * 256 + threadIdx.x;
    float4 v = ((const float4*)feats)[i];
    __nv_bfloat16 hx = __float2bfloat16(v.x), hy = __float2bfloat16(v.y);
    __nv_bfloat16 hz = __float2bfloat16(v.z), hw = __float2bfloat16(v.w);
    __nv_bfloat16 lx = __float2bfloat16(v.x - __bfloat162float(hx));
    __nv_bfloat16 ly = __float2bfloat16(v.y - __bfloat162float(hy));
    __nv_bfloat16 lz = __float2bfloat16(v.z - __bfloat162float(hz));
    __nv_bfloat16 lw = __float2bfloat16(v.w - __bfloat162float(hw));
    __nv_bfloat162* ph = (__nv_bfloat162*)g_a_hi;
    __nv_bfloat162* pl = (__nv_bfloat162*)g_a_lo;
    ph[2*i]   = __nv_bfloat162(hx, hy); ph[2*i+1] = __nv_bfloat162(hz, hw);
    pl[2*i]   = __nv_bfloat162(lx, ly); pl[2*i+1] = __nv_bfloat162(lz, lw);
}

// ---------------- prep: weights transpose + split ----------------
__global__ __launch_bounds__(256) void prep_w_kernel(
    const float* __restrict__ Wq, const float* __restrict__ Wk, const float* __restrict__ Wv)
{
    __shared__ float tile[32][33];
    const int which = blockIdx.z;
    const float* W = (which == 0) ? Wq : ((which == 1) ? Wk : Wv);
    const int n0 = blockIdx.x * 32, k0 = blockIdx.y * 32;
    const int tx = threadIdx.x & 31, ty = (threadIdx.x >> 5) * 4;
    #pragma unroll
    for (int i = 0; i < 4; i++)
        tile[ty + i][tx] = W[(size_t)(k0 + ty + i) * EDIM + n0 + tx];
    __syncthreads();
    #pragma unroll
    for (int i = 0; i < 4; i++) {
        const int n = n0 + ty + i, k = k0 + tx;
        const float v = tile[tx][ty + i];
        __nv_bfloat16 h = __float2bfloat16(v);
        __nv_bfloat16 l = __float2bfloat16(v - __bfloat162float(h));
        g_b_hi[(size_t)(which * EDIM + n) * EDIM + k] = h;
        g_b_lo[(size_t)(which * EDIM + n) * EDIM + k] = l;
    }
}

// ---------------- HMMA QKV GEMM: 128x256 tile, 512 threads, 3-stage ----------------
#define OFF_AHI 0
#define OFF_ALO 8192
#define OFF_BHI 16384
#define OFF_BLO 32768
#define STG 49152
#define GEMM_SMEM (3*STG)
#define NCHUNK (EDIM/32)

__device__ __forceinline__ uint32_t sw_addr(uint32_t tile, int row, int kc) {
    return tile + (row << 6) + ((kc ^ ((row >> 1) & 3)) << 4);
}

__global__ __launch_bounds__(512, 1) void qkv_mma_kernel(
    const float* __restrict__ bq, const float* __restrict__ bk, const float* __restrict__ bv)
{
    extern __shared__ char smem[];
    const uint32_t smem_base = smem_to_u32(smem);
    const int tid  = threadIdx.x;
    const int wid  = tid >> 5;
    const int lane = tid & 31;
    const int m0    = blockIdx.y * 128;
    const int nbase = blockIdx.x * 256;

    const int wm = wid & 1, wn = wid >> 1;     // 2 x 8 warp grid; warp tile 64x32
    const int mw = wm * 64, nw = wn * 32;
    const int lane7 = lane & 7, quad = lane >> 3;

    float c[4][4][4];
    #pragma unroll
    for (int i = 0; i < 4; i++)
        #pragma unroll
        for (int j = 0; j < 4; j++)
            #pragma unroll
            for (int r = 0; r < 4; r++) c[i][j][r] = 0.f;

    auto copy_stage = [&](int s) {
        const uint32_t sb = smem_base + (s % 3) * STG;
        const int k0 = s * 32;
        {   // A: 128 rows x 4 chunks = 512 cp per matrix
            const int row = tid >> 2, cc = tid & 3;
            const uint32_t soff = (row << 6) + ((cc ^ ((row >> 1) & 3)) << 4);
            const size_t ga = (size_t)(m0 + row) * EDIM + k0 + cc * 8;
            cp_async16(sb + OFF_AHI + soff, g_a_hi + ga);
            cp_async16(sb + OFF_ALO + soff, g_a_lo + ga);
        }
        #pragma unroll
        for (int i = 0; i < 2; i++) {  // B: 256 rows x 4 chunks = 1024 cp per matrix
            const int idx = tid + i * 512;
            const int row = idx >> 2, cc = idx & 3;
            const uint32_t soff = (row << 6) + ((cc ^ ((row >> 1) & 3)) << 4);
            const size_t gb = (size_t)(nbase + row) * EDIM + k0 + cc * 8;
            cp_async16(sb + OFF_BHI + soff, g_b_hi + gb);
            cp_async16(sb + OFF_BLO + soff, g_b_lo + gb);
        }
        asm volatile("cp.async.commit_group;" ::: "memory");
    };

    copy_stage(0);
    copy_stage(1);

    for (int ch = 0; ch < NCHUNK; ch++) {
        if (ch + 1 < NCHUNK) {
            asm volatile("cp.async.wait_group 1;" ::: "memory");
        } else {
            asm volatile("cp.async.wait_group 0;" ::: "memory");
        }
        __syncthreads();
        if (ch + 2 < NCHUNK) copy_stage(ch + 2);

        const uint32_t sb = smem_base + (ch % 3) * STG;
        #pragma unroll
        for (int ks = 0; ks < 2; ks++) {
            uint32_t bh[4][2], bl[4][2], a[4][4];
            #pragma unroll
            for (int j2 = 0; j2 < 2; j2++) {
                const int rowB = nw + j2 * 16 + ((quad >> 1) << 3) + lane7;
                const int kcB  = 2 * ks + (quad & 1);
                uint32_t r[4];
                ldsm4(r, sw_addr(sb + OFF_BHI, rowB, kcB));
                bh[2*j2][0] = r[0]; bh[2*j2][1] = r[1];
                bh[2*j2+1][0] = r[2]; bh[2*j2+1][1] = r[3];
                ldsm4(r, sw_addr(sb + OFF_BLO, rowB, kcB));
                bl[2*j2][0] = r[0]; bl[2*j2][1] = r[1];
                bl[2*j2+1][0] = r[2]; bl[2*j2+1][1] = r[3];
            }
            const int rowA_ = ((quad & 1) << 3) + lane7;
            const int kcA   = 2 * ks + (quad >> 1);
            #pragma unroll
            for (int i = 0; i < 4; i++)
                ldsm4(a[i], sw_addr(sb + OFF_AHI, mw + 16 * i + rowA_, kcA));
            #pragma unroll
            for (int i = 0; i < 4; i++)
                #pragma unroll
                for (int j = 0; j < 4; j++) {
                    mma16816(c[i][j], a[i], bh[j]);
                    mma16816(c[i][j], a[i], bl[j]);
                }
            #pragma unroll
            for (int i = 0; i < 4; i++)
                ldsm4(a[i], sw_addr(sb + OFF_ALO, mw + 16 * i + rowA_, kcA));
            #pragma unroll
            for (int i = 0; i < 4; i++)
                #pragma unroll
                for (int j = 0; j < 4; j++)
                    mma16816(c[i][j], a[i], bh[j]);
        }
        __syncthreads();
    }

    // ---- epilogue ----
    const int which = blockIdx.x / 3;            // 256-col tiles, 3 per projection
    const int ncol_off = which * EDIM;
    const float* bias = (which == 0) ? bq : ((which == 1) ? bk : bv);
    const float scale = (which == 0) ? 0.20412414523193154f : 1.0f;
    __nv_bfloat16* dsth = (which == 0) ? g_qh : g_kh;
    __nv_bfloat16* dstl = (which == 0) ? g_ql : g_kl;
    const int g  = lane >> 2;
    const int t4 = lane & 3;

    #pragma unroll
    for (int i = 0; i < 4; i++) {
        #pragma unroll
        for (int half = 0; half < 2; half++) {
            const int row = m0 + mw + 16 * i + g + 8 * half;
            const int bb = row >> 8, tt = row & 255;
            #pragma unroll
            for (int j = 0; j < 4; j++) {
                const int col = nbase + nw + 8 * j + 2 * t4 - ncol_off;
                float2 v;
                v.x = (c[i][j][2*half + 0] + bias[col])     * scale;
                v.y = (c[i][j][2*half + 1] + bias[col + 1]) * scale;
                if (which == 2) {
                    *(float2*)&g_v[(size_t)row * EDIM + col] = v;
                } else {
                    const int h = col / DDIM, d = col - h * DDIM;
                    const size_t off = ((size_t)(bb * HDIM + h) * SDIM + tt) * 32 + d;
                    __nv_bfloat16 hx = __float2bfloat16(v.x);
                    __nv_bfloat16 hy = __float2bfloat16(v.y);
                    __nv_bfloat16 lx = __float2bfloat16(v.x - __bfloat162float(hx));
                    __nv_bfloat16 ly = __float2bfloat16(v.y - __bfloat162float(hy));
                    *(__nv_bfloat162*)&dsth[off] = __nv_bfloat162(hx, hy);
                    *(__nv_bfloat162*)&dstl[off] = __nv_bfloat162(lx, ly);
                }
            }
        }
    }
}

// ---------------- vproj ----------------
__global__ __launch_bounds__(256) void vproj_kernel(
    const float* __restrict__ Wfx, const float* __restrict__ Wfy, const float* __restrict__ Wfz)
{
    const int row = blockIdx.x * 8 + (threadIdx.x >> 5);
    const int h   = threadIdx.x & 31;
    const float* v  = g_v + (size_t)row * EDIM + h * DDIM;
    const float* wx = Wfx + h * DDIM;
    const float* wy = Wfy + h * DDIM;
    const float* wz = Wfz + h * DDIM;
    float vx = 0.f, vy = 0.f, vz = 0.f;
    #pragma unroll
    for (int i = 0; i < 6; i++) {
        float4 vv = *(const float4*)(v  + 4 * i);
        float4 ax = *(const float4*)(wx + 4 * i);
        float4 ay = *(const float4*)(wy + 4 * i);
        float4 az = *(const float4*)(wz + 4 * i);
        vx += vv.x*ax.x + vv.y*ax.y + vv.z*ax.z + vv.w*ax.w;
        vy += vv.x*ay.x + vv.y*ay.y + vv.z*ay.z + vv.w*ay.w;
        vz += vv.x*az.x + vv.y*az.y + vv.z*az.z + vv.w*az.w;
    }
    const int b = row >> 8, t = row & 255;
    *(float4*)&g_vp[((size_t)(b * HDIM + h) * SDIM + t) * 4] = make_float4(vx, vy, vz, 0.f);
}

// ---------------- MMA attention: 3-stage cp.async pipeline ----------------
#define AKH   0
#define AKL   16384
#define AVP   32768
#define ABIA  36864
#define BROW  1040
#define ASTG  70400
#define AZP   (3*ASTG)
#define ARED  (3*ASTG + 2048)
#define ATTN_SMEM (3*ASTG + 2048 + 3072)

__global__ __launch_bounds__(512, 1) void attn_kernel(
    const float* __restrict__ attn_bias,
    const float* __restrict__ delta,
    float* __restrict__ out)
{
    extern __shared__ char sa[];
    const uint32_t sb = smem_to_u32(sa);
    const int b   = blockIdx.y;
    const int s0  = blockIdx.x * 32;
    const int tid = threadIdx.x;
    const int lane = tid & 31;
    const int wid  = tid >> 5;
    const int mh   = wid & 1;
    const int band = wid >> 1;
    const int nb   = band * 32;
    const int g    = lane >> 2;
    const int t4   = lane & 3;
    const int l8   = lane & 7, l8h = lane >> 3;

    auto stage = [&](int hh) {
        const uint32_t bufs = sb + (hh % 3) * ASTG;
        const size_t kbase = (size_t)(b * HDIM + hh) * SDIM * 32;
        #pragma unroll
        for (int i = 0; i < 2; i++) {
            const int m = tid + i * 512;
            const int r = m >> 2, c2 = m & 3;
            const uint32_t so = (r << 6) + ((c2 ^ ((r >> 1) & 3)) << 4);
            cp_async16(bufs + AKH + so, g_kh + kbase + r * 32 + c2 * 8);
            cp_async16(bufs + AKL + so, g_kl + kbase + r * 32 + c2 * 8);
        }
        if (tid < 256)
            cp_async16(bufs + AVP + tid * 16,
                       g_vp + (size_t)(b * HDIM + hh) * SDIM * 4 + tid * 4);
        const float* bsrc = attn_bias + (((size_t)b * HDIM + hh) * SDIM + s0) * SDIM;
        #pragma unroll
        for (int i = 0; i < 4; i++) {
            const int m = tid + i * 512;
            const int r = m >> 6, cc = m & 63;
            cp_async16(bufs + ABIA + r * BROW + cc * 16, bsrc + (size_t)r * SDIM + cc * 4);
        }
        asm volatile("cp.async.commit_group;" ::: "memory");
    };

    float G[2][4][2][3];
    #pragma unroll
    for (int r = 0; r < 2; r++)
        #pragma unroll
        for (int j = 0; j < 4; j++)
            #pragma unroll
            for (int cc = 0; cc < 2; cc++)
                #pragma unroll
                for (int x = 0; x < 3; x++) G[r][j][cc][x] = 0.f;

    stage(0);
    stage(1);

    for (int h = 0; h < HDIM; h++) {
        const int par = h & 1;
        if (h + 1 < HDIM) {
            asm volatile("cp.async.wait_group 1;" ::: "memory");
        } else {
            asm volatile("cp.async.wait_group 0;" ::: "memory");
        }
        __syncthreads();    // stage h visible; buffer (h+2)%3 fully consumed
        if (h + 2 < HDIM) stage(h + 2);

        // q fragments direct from gmem (packed bf16 hi/lo, pad cols are zero)
        const size_t qoff = ((size_t)(b * HDIM + h) * SDIM + s0 + mh * 16) * 32;
        const __nv_bfloat16* qh = g_qh + qoff;
        const __nv_bfloat16* ql = g_ql + qoff;
        uint32_t ah[2][4], al[2][4];
        #pragma unroll
        for (int kk = 0; kk < 2; kk++) {
            const int kb = 16 * kk + 2 * t4;
            ah[kk][0] = *(const uint32_t*)&qh[(g)     * 32 + kb];
            ah[kk][1] = *(const uint32_t*)&qh[(g + 8) * 32 + kb];
            ah[kk][2] = *(const uint32_t*)&qh[(g)     * 32 + kb + 8];
            ah[kk][3] = *(const uint32_t*)&qh[(g + 8) * 32 + kb + 8];
            al[kk][0] = *(const uint32_t*)&ql[(g)     * 32 + kb];
            al[kk][1] = *(const uint32_t*)&ql[(g + 8) * 32 + kb];
            al[kk][2] = *(const uint32_t*)&ql[(g)     * 32 + kb + 8];
            al[kk][3] = *(const uint32_t*)&ql[(g + 8) * 32 + kb + 8];
        }

        const uint32_t bufs = sb + (h % 3) * ASTG;

        float c[4][4];
        #pragma unroll
        for (int j = 0; j < 4; j++)
            #pragma unroll
            for (int r = 0; r < 4; r++) c[j][r] = 0.f;

        #pragma unroll
        for (int j = 0; j < 4; j++) {
            uint32_t bh[4], bl[4];
            const int rowB = nb + j * 8 + l8;
            const uint32_t so = (rowB << 6) + ((l8h ^ ((rowB >> 1) & 3)) << 4);
            ldsm4(bh, bufs + AKH + so);
            ldsm4(bl, bufs + AKL + so);
            mma16816(c[j], ah[0], bh);
            mma16816(c[j], ah[1], bh + 2);
            mma16816(c[j], ah[0], bl);
            mma16816(c[j], ah[1], bl + 2);
            mma16816(c[j], al[0], bh);
            mma16816(c[j], al[1], bh + 2);
        }

        // bias (smem) + exp + row partial sums
        const char* bp0 = sa + (h % 3) * ASTG + ABIA + (mh * 16 + g) * BROW + (nb + 2 * t4) * 4;
        const char* bp1 = bp0 + 8 * BROW;
        float ps0 = 0.f, ps1 = 0.f;
        #pragma unroll
        for (int j = 0; j < 4; j++) {
            float2 b0 = *(const float2*)(bp0 + 32 * j);
            float2 b1 = *(const float2*)(bp1 + 32 * j);
            c[j][0] = __expf(c[j][0] + b0.x);
            c[j][1] = __expf(c[j][1] + b0.y);
            c[j][2] = __expf(c[j][2] + b1.x);
            c[j][3] = __expf(c[j][3] + b1.y);
            ps0 += c[j][0] + c[j][1];
            ps1 += c[j][2] + c[j][3];
        }
        ps0 += __shfl_xor_sync(0xffffffffu, ps0, 1);
        ps0 += __shfl_xor_sync(0xffffffffu, ps0, 2);
        ps1 += __shfl_xor_sync(0xffffffffu, ps1, 1);
        ps1 += __shfl_xor_sync(0xffffffffu, ps1, 2);
        float* zp = (float*)(sa + AZP + par * 1024);
        if (t4 == 0) {
            zp[(mh * 16 + g) * 8 + band]     = ps0;
            zp[(mh * 16 + g + 8) * 8 + band] = ps1;
        }
        __syncthreads();

        float Z0, Z1;
        {
            float4 a0 = *(float4*)(zp + (mh * 16 + g) * 8);
            float4 a1 = *(float4*)(zp + (mh * 16 + g) * 8 + 4);
            Z0 = (a0.x + a0.y) + (a0.z + a0.w) + (a1.x + a1.y) + (a1.z + a1.w);
            float4 b0 = *(float4*)(zp + (mh * 16 + g + 8) * 8);
            float4 b1 = *(float4*)(zp + (mh * 16 + g + 8) * 8 + 4);
            Z1 = (b0.x + b0.y) + (b0.z + b0.w) + (b1.x + b1.y) + (b1.z + b1.w);
        }
        const float iz0 = __fdividef(1.f, Z0);
        const float iz1 = __fdividef(1.f, Z1);

        #pragma unroll
        for (int j = 0; j < 4; j++) {
            const char* vpp = sa + (h % 3) * ASTG + AVP + (nb + 8 * j + 2 * t4) * 16;
            float4 v0 = *(const float4*)vpp;
            float4 v1 = *(const float4*)(vpp + 16);
            const float p00 = c[j][0] * iz0, p01 = c[j][1] * iz0;
            const float p10 = c[j][2] * iz1, p11 = c[j][3] * iz1;
            G[0][j][0][0] = fmaf(p00, v0.x, G[0][j][0][0]);
            G[0][j][0][1] = fmaf(p00, v0.y, G[0][j][0][1]);
            G[0][j][0][2] = fmaf(p00, v0.z, G[0][j][0][2]);
            G[0][j][1][0] = fmaf(p01, v1.x, G[0][j][1][0]);
            G[0][j][1][1] = fmaf(p01, v1.y, G[0][j][1][1]);
            G[0][j][1][2] = fmaf(p01, v1.z, G[0][j][1][2]);
            G[1][j][0][0] = fmaf(p10, v0.x, G[1][j][0][0]);
            G[1][j][0][1] = fmaf(p10, v0.y, G[1][j][0][1]);
            G[1][j][0][2] = fmaf(p10, v0.z, G[1][j][0][2]);
            G[1][j][1][0] = fmaf(p11, v1.x, G[1][j][1][0]);
            G[1][j][1][1] = fmaf(p11, v1.y, G[1][j][1][1]);
            G[1][j][1][2] = fmaf(p11, v1.z, G[1][j][1][2]);
        }
    }

    // ---- delta contraction + output ----
    float ox[2] = {0.f, 0.f}, oy[2] = {0.f, 0.f}, oz[2] = {0.f, 0.f};
    #pragma unroll
    for (int rh = 0; rh < 2; rh++) {
        const int srow = s0 + mh * 16 + g + 8 * rh;
        const float* dp = delta + (size_t)(b * SDIM + srow) * SDIM * 3;
        #pragma unroll
        for (int j = 0; j < 4; j++) {
            const int t0 = nb + 8 * j + 2 * t4;
            const float* d0 = dp + t0 * 3;
            ox[rh] += G[rh][j][0][0] * d0[0] + G[rh][j][1][0] * d0[3];
            oy[rh] += G[rh][j][0][1] * d0[1] + G[rh][j][1][1] * d0[4];
            oz[rh] += G[rh][j][0][2] * d0[2] + G[rh][j][1][2] * d0[5];
        }
    }
    #pragma unroll
    for (int rh = 0; rh < 2; rh++) {
        ox[rh] += __shfl_xor_sync(0xffffffffu, ox[rh], 1);
        ox[rh] += __shfl_xor_sync(0xffffffffu, ox[rh], 2);
        oy[rh] += __shfl_xor_sync(0xffffffffu, oy[rh], 1);
        oy[rh] += __shfl_xor_sync(0xffffffffu, oy[rh], 2);
        oz[rh] += __shfl_xor_sync(0xffffffffu, oz[rh], 1);
        oz[rh] += __shfl_xor_sync(0xffffffffu, oz[rh], 2);
    }
    float* red = (float*)(sa + ARED);
    if (t4 == 0) {
        #pragma unroll
        for (int rh = 0; rh < 2; rh++) {
            const int row = mh * 16 + g + 8 * rh;
            red[(row * 8 + band) * 3 + 0] = ox[rh];
            red[(row * 8 + band) * 3 + 1] = oy[rh];
            red[(row * 8 + band) * 3 + 2] = oz[rh];
        }
    }
    __syncthreads();
    if (tid < 96) {
        const int row = tid / 3, x = tid % 3;
        float s = 0.f;
        #pragma unroll
        for (int k = 0; k < 8; k++) s += red[(row * 8 + k) * 3 + x];
        out[((size_t)(b * SDIM) + s0 + row) * 3 + x] = s;
    }
}

// ---------------- launch ----------------
extern "C" void kernel_launch(void* const* d_in, const int* in_sizes, int n_in,
                              void* d_out, int out_size)
{
    const float* feats     = (const float*)d_in[0];
    const float* attn_bias = (const float*)d_in[1];
    const float* delta     = (const float*)d_in[2];
    const float* Wq  = (const float*)d_in[3];
    const float* bq  = (const float*)d_in[4];
    const float* Wk  = (const float*)d_in[5];
    const float* bk  = (const float*)d_in[6];
    const float* Wv  = (const float*)d_in[7];
    const float* bv  = (const float*)d_in[8];
    const float* Wfx = (const float*)d_in[9];
    const float* Wfy = (const float*)d_in[10];
    const float* Wfz = (const float*)d_in[11];
    float* out = (float*)d_out;

    prep_a_kernel<<<(ROWS * EDIM / 4) / 256, 256>>>(feats);
    prep_w_kernel<<<dim3(EDIM / 32, EDIM / 32, 3), 256>>>(Wq, Wk, Wv);

    cudaFuncSetAttribute(qkv_mma_kernel, cudaFuncAttributeMaxDynamicSharedMemorySize, GEMM_SMEM);
    dim3 gg(QKVN / 256, ROWS / 128);   // (9, 64)
    qkv_mma_kernel<<<gg, 512, GEMM_SMEM>>>(bq, bk, bv);

    vproj_kernel<<<ROWS / 8, 256>>>(Wfx, Wfy, Wfz);

    cudaFuncSetAttribute(attn_kernel, cudaFuncAttributeMaxDynamicSharedMemorySize, ATTN_SMEM);
    dim3 g2(SDIM / 32, BDIM);
    attn_kernel<<<g2, 512, ATTN_SMEM>>>(attn_bias, delta, out);
}

// round 10
// speedup vs baseline: 1.1728x; 1.1728x over previous
#include <cuda_runtime.h>
#include <cuda_bf16.h>
#include <cstdint>
#include <math.h>

#define BDIM 32
#define SDIM 256
#define EDIM 768
#define HDIM 32
#define DDIM 24
#define ROWS (BDIM*SDIM)     /* 8192 */
#define QKVN (3*EDIM)        /* 2304 */

// ---------------- device scratch ----------------
__device__ __align__(16) __nv_bfloat16 g_a_hi[(size_t)ROWS * EDIM];
__device__ __align__(16) __nv_bfloat16 g_a_lo[(size_t)ROWS * EDIM];
__device__ __align__(16) __nv_bfloat16 g_b_hi[(size_t)QKVN * EDIM];   // wt[n][k]
__device__ __align__(16) __nv_bfloat16 g_b_lo[(size_t)QKVN * EDIM];
// q/k in attn-ready packed bf16 hi/lo: [b][h][s][32] (cols 24..31 stay zero)
__device__ __align__(16) __nv_bfloat16 g_qh[(size_t)ROWS * HDIM * 32];
__device__ __align__(16) __nv_bfloat16 g_ql[(size_t)ROWS * HDIM * 32];
__device__ __align__(16) __nv_bfloat16 g_kh[(size_t)ROWS * HDIM * 32];
__device__ __align__(16) __nv_bfloat16 g_kl[(size_t)ROWS * HDIM * 32];
__device__ float g_v [(size_t)ROWS * EDIM];
__device__ float g_vp[(size_t)ROWS * HDIM * 4];

// ---------------- PTX helpers (base sm_80+ ISA only) ----------------
__device__ __forceinline__ uint32_t smem_to_u32(const void* p) {
    uint32_t a;
    asm("{ .reg .u64 t; cvta.to.shared.u64 t, %1; cvt.u32.u64 %0, t; }" : "=r"(a) : "l"(p));
    return a;
}
__device__ __forceinline__ void cp_async16(uint32_t s, const void* g) {
    asm volatile("cp.async.cg.shared.global [%0], [%1], 16;" :: "r"(s), "l"(g) : "memory");
}
__device__ __forceinline__ void ldsm4(uint32_t* r, uint32_t addr) {
    asm volatile("ldmatrix.sync.aligned.m8n8.x4.shared.b16 {%0,%1,%2,%3}, [%4];"
                 : "=r"(r[0]), "=r"(r[1]), "=r"(r[2]), "=r"(r[3]) : "r"(addr));
}
__device__ __forceinline__ void mma16816(float* c, const uint32_t* a, const uint32_t* b) {
    asm volatile("mma.sync.aligned.m16n8k16.row.col.f32.bf16.bf16.f32 "
                 "{%0,%1,%2,%3}, {%4,%5,%6,%7}, {%8,%9}, {%0,%1,%2,%3};"
                 : "+f"(c[0]), "+f"(c[1]), "+f"(c[2]), "+f"(c[3])
                 : "r"(a[0]), "r"(a[1]), "r"(a[2]), "r"(a[3]), "r"(b[0]), "r"(b[1]));
}

// ---------------- prep: feats -> bf16 hi/lo ----------------
__global__ __launch_bounds__(256) void prep_a_kernel(const float* __restrict__ feats)
{
    const size_t i = (size_t)blockIdx.x * 256 + threadIdx.x;
    float4 v = ((const float4*)feats)[i];
    __nv_bfloat16 hx = __float2bfloat16(v.x), hy = __float2bfloat16(v.y);
    __nv_bfloat16 hz = __float2bfloat16(v.z), hw = __float2bfloat16(v.w);
    __nv_bfloat16 lx = __float2bfloat16(v.x - __bfloat162float(hx));
    __nv_bfloat16 ly = __float2bfloat16(v.y - __bfloat162float(hy));
    __nv_bfloat16 lz = __float2bfloat16(v.z - __bfloat162float(hz));
    __nv_bfloat16 lw = __float2bfloat16(v.w - __bfloat162float(hw));
    __nv_bfloat162* ph = (__nv_bfloat162*)g_a_hi;
    __nv_bfloat162* pl = (__nv_bfloat162*)g_a_lo;
    ph[2*i]   = __nv_bfloat162(hx, hy); ph[2*i+1] = __nv_bfloat162(hz, hw);
    pl[2*i]   = __nv_bfloat162(lx, ly); pl[2*i+1] = __nv_bfloat162(lz, lw);
}

// ---------------- prep: weights transpose + split ----------------
__global__ __launch_bounds__(256) void prep_w_kernel(
    const float* __restrict__ Wq, const float* __restrict__ Wk, const float* __restrict__ Wv)
{
    __shared__ float tile[32][33];
    const int which = blockIdx.z;
    const float* W = (which == 0) ? Wq : ((which == 1) ? Wk : Wv);
    const int n0 = blockIdx.x * 32, k0 = blockIdx.y * 32;
    const int tx = threadIdx.x & 31, ty = (threadIdx.x >> 5) * 4;
    #pragma unroll
    for (int i = 0; i < 4; i++)
        tile[ty + i][tx] = W[(size_t)(k0 + ty + i) * EDIM + n0 + tx];
    __syncthreads();
    #pragma unroll
    for (int i = 0; i < 4; i++) {
        const int n = n0 + ty + i, k = k0 + tx;
        const float v = tile[tx][ty + i];
        __nv_bfloat16 h = __float2bfloat16(v);
        __nv_bfloat16 l = __float2bfloat16(v - __bfloat162float(h));
        g_b_hi[(size_t)(which * EDIM + n) * EDIM + k] = h;
        g_b_lo[(size_t)(which * EDIM + n) * EDIM + k] = l;
    }
}

// ---------------- HMMA QKV GEMM: 128x128 tile, 256 thr, 3-stage (R7 config) ----------------
#define OFF_AHI 0
#define OFF_ALO 8192
#define OFF_BHI 16384
#define OFF_BLO 24576
#define STG 32768
#define GEMM_SMEM (3*STG)
#define NCHUNK (EDIM/32)

__device__ __forceinline__ uint32_t sw_addr(uint32_t tile, int row, int kc) {
    return tile + (row << 6) + ((kc ^ ((row >> 1) & 3)) << 4);
}

__global__ __launch_bounds__(256, 2) void qkv_mma_kernel(
    const float* __restrict__ bq, const float* __restrict__ bk, const float* __restrict__ bv)
{
    extern __shared__ char smem[];
    const uint32_t smem_base = smem_to_u32(smem);
    const int tid  = threadIdx.x;
    const int wid  = tid >> 5;
    const int lane = tid & 31;
    const int m0    = blockIdx.y * 128;
    const int nbase = blockIdx.x * 128;

    const int wm = wid & 1, wn = wid >> 1;
    const int mw = wm * 64, nw = wn * 32;
    const int lane7 = lane & 7, quad = lane >> 3;

    float c[4][4][4];
    #pragma unroll
    for (int i = 0; i < 4; i++)
        #pragma unroll
        for (int j = 0; j < 4; j++)
            #pragma unroll
            for (int r = 0; r < 4; r++) c[i][j][r] = 0.f;

    auto copy_stage = [&](int s) {
        const uint32_t sb = smem_base + (s % 3) * STG;
        const int k0 = s * 32;
        #pragma unroll
        for (int i = 0; i < 2; i++) {
            const int idx = tid + i * 256;
            const int row = idx >> 2, cc = idx & 3;
            const uint32_t soff = (row << 6) + ((cc ^ ((row >> 1) & 3)) << 4);
            const size_t ga = (size_t)(m0 + row) * EDIM + k0 + cc * 8;
            const size_t gb = (size_t)(nbase + row) * EDIM + k0 + cc * 8;
            cp_async16(sb + OFF_AHI + soff, g_a_hi + ga);
            cp_async16(sb + OFF_ALO + soff, g_a_lo + ga);
            cp_async16(sb + OFF_BHI + soff, g_b_hi + gb);
            cp_async16(sb + OFF_BLO + soff, g_b_lo + gb);
        }
        asm volatile("cp.async.commit_group;" ::: "memory");
    };

    copy_stage(0);
    copy_stage(1);

    for (int ch = 0; ch < NCHUNK; ch++) {
        if (ch + 1 < NCHUNK) {
            asm volatile("cp.async.wait_group 1;" ::: "memory");
        } else {
            asm volatile("cp.async.wait_group 0;" ::: "memory");
        }
        __syncthreads();
        if (ch + 2 < NCHUNK) copy_stage(ch + 2);

        const uint32_t sb = smem_base + (ch % 3) * STG;
        #pragma unroll
        for (int ks = 0; ks < 2; ks++) {
            uint32_t bh[4][2], bl[4][2], a[4][4];
            #pragma unroll
            for (int j2 = 0; j2 < 2; j2++) {
                const int rowB = nw + j2 * 16 + ((quad >> 1) << 3) + lane7;
                const int kcB  = 2 * ks + (quad & 1);
                uint32_t r[4];
                ldsm4(r, sw_addr(sb + OFF_BHI, rowB, kcB));
                bh[2*j2][0] = r[0]; bh[2*j2][1] = r[1];
                bh[2*j2+1][0] = r[2]; bh[2*j2+1][1] = r[3];
                ldsm4(r, sw_addr(sb + OFF_BLO, rowB, kcB));
                bl[2*j2][0] = r[0]; bl[2*j2][1] = r[1];
                bl[2*j2+1][0] = r[2]; bl[2*j2+1][1] = r[3];
            }
            const int rowA_ = ((quad & 1) << 3) + lane7;
            const int kcA   = 2 * ks + (quad >> 1);
            #pragma unroll
            for (int i = 0; i < 4; i++)
                ldsm4(a[i], sw_addr(sb + OFF_AHI, mw + 16 * i + rowA_, kcA));
            #pragma unroll
            for (int i = 0; i < 4; i++)
                #pragma unroll
                for (int j = 0; j < 4; j++) {
                    mma16816(c[i][j], a[i], bh[j]);
                    mma16816(c[i][j], a[i], bl[j]);
                }
            #pragma unroll
            for (int i = 0; i < 4; i++)
                ldsm4(a[i], sw_addr(sb + OFF_ALO, mw + 16 * i + rowA_, kcA));
            #pragma unroll
            for (int i = 0; i < 4; i++)
                #pragma unroll
                for (int j = 0; j < 4; j++)
                    mma16816(c[i][j], a[i], bh[j]);
        }
        __syncthreads();
    }

    // ---- epilogue ----
    const int which = blockIdx.x / 6;
    const int ncol_off = which * EDIM;
    const float* bias = (which == 0) ? bq : ((which == 1) ? bk : bv);
    const float scale = (which == 0) ? 0.20412414523193154f : 1.0f;
    __nv_bfloat16* dsth = (which == 0) ? g_qh : g_kh;
    __nv_bfloat16* dstl = (which == 0) ? g_ql : g_kl;
    const int g  = lane >> 2;
    const int t4 = lane & 3;

    #pragma unroll
    for (int i = 0; i < 4; i++) {
        #pragma unroll
        for (int half = 0; half < 2; half++) {
            const int row = m0 + mw + 16 * i + g + 8 * half;
            const int bb = row >> 8, tt = row & 255;
            #pragma unroll
            for (int j = 0; j < 4; j++) {
                const int col = nbase + nw + 8 * j + 2 * t4 - ncol_off;
                float2 v;
                v.x = (c[i][j][2*half + 0] + bias[col])     * scale;
                v.y = (c[i][j][2*half + 1] + bias[col + 1]) * scale;
                if (which == 2) {
                    *(float2*)&g_v[(size_t)row * EDIM + col] = v;
                } else {
                    const int h = col / DDIM, d = col - h * DDIM;
                    const size_t off = ((size_t)(bb * HDIM + h) * SDIM + tt) * 32 + d;
                    __nv_bfloat16 hx = __float2bfloat16(v.x);
                    __nv_bfloat16 hy = __float2bfloat16(v.y);
                    __nv_bfloat16 lx = __float2bfloat16(v.x - __bfloat162float(hx));
                    __nv_bfloat16 ly = __float2bfloat16(v.y - __bfloat162float(hy));
                    *(__nv_bfloat162*)&dsth[off] = __nv_bfloat162(hx, hy);
                    *(__nv_bfloat162*)&dstl[off] = __nv_bfloat162(lx, ly);
                }
            }
        }
    }
}

// ---------------- vproj ----------------
__global__ __launch_bounds__(256) void vproj_kernel(
    const float* __restrict__ Wfx, const float* __restrict__ Wfy, const float* __restrict__ Wfz)
{
    const int row = blockIdx.x * 8 + (threadIdx.x >> 5);
    const int h   = threadIdx.x & 31;
    const float* v  = g_v + (size_t)row * EDIM + h * DDIM;
    const float* wx = Wfx + h * DDIM;
    const float* wy = Wfy + h * DDIM;
    const float* wz = Wfz + h * DDIM;
    float vx = 0.f, vy = 0.f, vz = 0.f;
    #pragma unroll
    for (int i = 0; i < 6; i++) {
        float4 vv = *(const float4*)(v  + 4 * i);
        float4 ax = *(const float4*)(wx + 4 * i);
        float4 ay = *(const float4*)(wy + 4 * i);
        float4 az = *(const float4*)(wz + 4 * i);
        vx += vv.x*ax.x + vv.y*ax.y + vv.z*ax.z + vv.w*ax.w;
        vy += vv.x*ay.x + vv.y*ay.y + vv.z*ay.z + vv.w*ay.w;
        vz += vv.x*az.x + vv.y*az.y + vv.z*az.z + vv.w*az.w;
    }
    const int b = row >> 8, t = row & 255;
    *(float4*)&g_vp[((size_t)(b * HDIM + h) * SDIM + t) * 4] = make_float4(vx, vy, vz, 0.f);
}

// ---------------- MMA attention: 16 s-rows/block, 256 thr, 2 blocks/SM ----------------
#define AKH   0
#define AKL   16384
#define AVP   32768
#define ABIA  36864
#define BROW  1040
#define ASTG  53504     /* 36864 + 16*1040 = 53504 */
#define AZP   (2*ASTG)                 /* 2 x 512B */
#define ARED  (2*ASTG + 1024)          /* 16*8*3 floats = 1536B */
#define ATTN_SMEM (2*ASTG + 1024 + 1536)

__global__ __launch_bounds__(256, 2) void attn_kernel(
    const float* __restrict__ attn_bias,
    const float* __restrict__ delta,
    float* __restrict__ out)
{
    extern __shared__ char sa[];
    const uint32_t sb = smem_to_u32(sa);
    const int b   = blockIdx.y;
    const int s0  = blockIdx.x * 16;
    const int tid = threadIdx.x;
    const int lane = tid & 31;
    const int band = tid >> 5;           // warp id 0..7 = t band
    const int nb   = band * 32;
    const int g    = lane >> 2;
    const int t4   = lane & 3;
    const int l8   = lane & 7, l8h = lane >> 3;

    auto stage = [&](int hh) {
        const uint32_t bufs = sb + (hh & 1) * ASTG;
        const size_t kbase = (size_t)(b * HDIM + hh) * SDIM * 32;
        #pragma unroll
        for (int i = 0; i < 4; i++) {
            const int m = tid + i * 256;         // 0..1023
            const int r = m >> 2, c2 = m & 3;
            const uint32_t so = (r << 6) + ((c2 ^ ((r >> 1) & 3)) << 4);
            cp_async16(bufs + AKH + so, g_kh + kbase + r * 32 + c2 * 8);
            cp_async16(bufs + AKL + so, g_kl + kbase + r * 32 + c2 * 8);
        }
        cp_async16(bufs + AVP + tid * 16,
                   g_vp + (size_t)(b * HDIM + hh) * SDIM * 4 + tid * 4);
        const float* bsrc = attn_bias + (((size_t)b * HDIM + hh) * SDIM + s0) * SDIM;
        #pragma unroll
        for (int i = 0; i < 4; i++) {
            const int m = tid + i * 256;         // 0..1023 over 16 rows x 64 chunks
            const int r = m >> 6, cc = m & 63;
            cp_async16(bufs + ABIA + r * BROW + cc * 16, bsrc + (size_t)r * SDIM + cc * 4);
        }
        asm volatile("cp.async.commit_group;" ::: "memory");
    };

    float G[2][4][2][3];
    #pragma unroll
    for (int r = 0; r < 2; r++)
        #pragma unroll
        for (int j = 0; j < 4; j++)
            #pragma unroll
            for (int cc = 0; cc < 2; cc++)
                #pragma unroll
                for (int x = 0; x < 3; x++) G[r][j][cc][x] = 0.f;

    stage(0);

    for (int h = 0; h < HDIM; h++) {
        const int par = h & 1;
        asm volatile("cp.async.wait_group 0;" ::: "memory");
        __syncthreads();    // stage h visible; buffer 1-par free (prior head done)
        if (h + 1 < HDIM) stage(h + 1);

        // q fragments direct from gmem (packed bf16 hi/lo, pad cols are zero)
        const size_t qoff = ((size_t)(b * HDIM + h) * SDIM + s0) * 32;
        const __nv_bfloat16* qh = g_qh + qoff;
        const __nv_bfloat16* ql = g_ql + qoff;
        uint32_t ah[2][4], al[2][4];
        #pragma unroll
        for (int kk = 0; kk < 2; kk++) {
            const int kb = 16 * kk + 2 * t4;
            ah[kk][0] = *(const uint32_t*)&qh[(g)     * 32 + kb];
            ah[kk][1] = *(const uint32_t*)&qh[(g + 8) * 32 + kb];
            ah[kk][2] = *(const uint32_t*)&qh[(g)     * 32 + kb + 8];
            ah[kk][3] = *(const uint32_t*)&qh[(g + 8) * 32 + kb + 8];
            al[kk][0] = *(const uint32_t*)&ql[(g)     * 32 + kb];
            al[kk][1] = *(const uint32_t*)&ql[(g + 8) * 32 + kb];
            al[kk][2] = *(const uint32_t*)&ql[(g)     * 32 + kb + 8];
            al[kk][3] = *(const uint32_t*)&ql[(g + 8) * 32 + kb + 8];
        }

        const uint32_t bufs = sb + par * ASTG;

        float c[4][4];
        #pragma unroll
        for (int j = 0; j < 4; j++)
            #pragma unroll
            for (int r = 0; r < 4; r++) c[j][r] = 0.f;

        #pragma unroll
        for (int j = 0; j < 4; j++) {
            uint32_t bh[4], bl[4];
            const int rowB = nb + j * 8 + l8;
            const uint32_t so = (rowB << 6) + ((l8h ^ ((rowB >> 1) & 3)) << 4);
            ldsm4(bh, bufs + AKH + so);
            ldsm4(bl, bufs + AKL + so);
            mma16816(c[j], ah[0], bh);
            mma16816(c[j], ah[1], bh + 2);
            mma16816(c[j], ah[0], bl);
            mma16816(c[j], ah[1], bl + 2);
            mma16816(c[j], al[0], bh);
            mma16816(c[j], al[1], bh + 2);
        }

        // bias (smem) + exp + row partial sums
        const char* bp0 = sa + par * ASTG + ABIA + g * BROW + (nb + 2 * t4) * 4;
        const char* bp1 = bp0 + 8 * BROW;
        float ps0 = 0.f, ps1 = 0.f;
        #pragma unroll
        for (int j = 0; j < 4; j++) {
            float2 b0 = *(const float2*)(bp0 + 32 * j);
            float2 b1 = *(const float2*)(bp1 + 32 * j);
            c[j][0] = __expf(c[j][0] + b0.x);
            c[j][1] = __expf(c[j][1] + b0.y);
            c[j][2] = __expf(c[j][2] + b1.x);
            c[j][3] = __expf(c[j][3] + b1.y);
            ps0 += c[j][0] + c[j][1];
            ps1 += c[j][2] + c[j][3];
        }
        ps0 += __shfl_xor_sync(0xffffffffu, ps0, 1);
        ps0 += __shfl_xor_sync(0xffffffffu, ps0, 2);
        ps1 += __shfl_xor_sync(0xffffffffu, ps1, 1);
        ps1 += __shfl_xor_sync(0xffffffffu, ps1, 2);
        float* zp = (float*)(sa + AZP + par * 512);
        if (t4 == 0) {
            zp[(g)     * 8 + band] = ps0;
            zp[(g + 8) * 8 + band] = ps1;
        }
        __syncthreads();

        float Z0, Z1;
        {
            float4 a0 = *(float4*)(zp + g * 8);
            float4 a1 = *(float4*)(zp + g * 8 + 4);
            Z0 = (a0.x + a0.y) + (a0.z + a0.w) + (a1.x + a1.y) + (a1.z + a1.w);
            float4 b0 = *(float4*)(zp + (g + 8) * 8);
            float4 b1 = *(float4*)(zp + (g + 8) * 8 + 4);
            Z1 = (b0.x + b0.y) + (b0.z + b0.w) + (b1.x + b1.y) + (b1.z + b1.w);
        }
        const float iz0 = __fdividef(1.f, Z0);
        const float iz1 = __fdividef(1.f, Z1);

        #pragma unroll
        for (int j = 0; j < 4; j++) {
            const char* vpp = sa + par * ASTG + AVP + (nb + 8 * j + 2 * t4) * 16;
            float4 v0 = *(const float4*)vpp;
            float4 v1 = *(const float4*)(vpp + 16);
            const float p00 = c[j][0] * iz0, p01 = c[j][1] * iz0;
            const float p10 = c[j][2] * iz1, p11 = c[j][3] * iz1;
            G[0][j][0][0] = fmaf(p00, v0.x, G[0][j][0][0]);
            G[0][j][0][1] = fmaf(p00, v0.y, G[0][j][0][1]);
            G[0][j][0][2] = fmaf(p00, v0.z, G[0][j][0][2]);
            G[0][j][1][0] = fmaf(p01, v1.x, G[0][j][1][0]);
            G[0][j][1][1] = fmaf(p01, v1.y, G[0][j][1][1]);
            G[0][j][1][2] = fmaf(p01, v1.z, G[0][j][1][2]);
            G[1][j][0][0] = fmaf(p10, v0.x, G[1][j][0][0]);
            G[1][j][0][1] = fmaf(p10, v0.y, G[1][j][0][1]);
            G[1][j][0][2] = fmaf(p10, v0.z, G[1][j][0][2]);
            G[1][j][1][0] = fmaf(p11, v1.x, G[1][j][1][0]);
            G[1][j][1][1] = fmaf(p11, v1.y, G[1][j][1][1]);
            G[1][j][1][2] = fmaf(p11, v1.z, G[1][j][1][2]);
        }
    }

    // ---- delta contraction + output ----
    float ox[2] = {0.f, 0.f}, oy[2] = {0.f, 0.f}, oz[2] = {0.f, 0.f};
    #pragma unroll
    for (int rh = 0; rh < 2; rh++) {
        const int srow = s0 + g + 8 * rh;
        const float* dp = delta + (size_t)(b * SDIM + srow) * SDIM * 3;
        #pragma unroll
        for (int j = 0; j < 4; j++) {
            const int t0 = nb + 8 * j + 2 * t4;
            const float* d0 = dp + t0 * 3;
            ox[rh] += G[rh][j][0][0] * d0[0] + G[rh][j][1][0] * d0[3];
            oy[rh] += G[rh][j][0][1] * d0[1] + G[rh][j][1][1] * d0[4];
            oz[rh] += G[rh][j][0][2] * d0[2] + G[rh][j][1][2] * d0[5];
        }
    }
    #pragma unroll
    for (int rh = 0; rh < 2; rh++) {
        ox[rh] += __shfl_xor_sync(0xffffffffu, ox[rh], 1);
        ox[rh] += __shfl_xor_sync(0xffffffffu, ox[rh], 2);
        oy[rh] += __shfl_xor_sync(0xffffffffu, oy[rh], 1);
        oy[rh] += __shfl_xor_sync(0xffffffffu, oy[rh], 2);
        oz[rh] += __shfl_xor_sync(0xffffffffu, oz[rh], 1);
        oz[rh] += __shfl_xor_sync(0xffffffffu, oz[rh], 2);
    }
    float* red = (float*)(sa + ARED);
    if (t4 == 0) {
        #pragma unroll
        for (int rh = 0; rh < 2; rh++) {
            const int row = g + 8 * rh;
            red[(row * 8 + band) * 3 + 0] = ox[rh];
            red[(row * 8 + band) * 3 + 1] = oy[rh];
            red[(row * 8 + band) * 3 + 2] = oz[rh];
        }
    }
    __syncthreads();
    if (tid < 48) {
        const int row = tid / 3, x = tid % 3;
        float s = 0.f;
        #pragma unroll
        for (int k = 0; k < 8; k++) s += red[(row * 8 + k) * 3 + x];
        out[((size_t)(b * SDIM) + s0 + row) * 3 + x] = s;
    }
}

// ---------------- launch ----------------
extern "C" void kernel_launch(void* const* d_in, const int* in_sizes, int n_in,
                              void* d_out, int out_size)
{
    const float* feats     = (const float*)d_in[0];
    const float* attn_bias = (const float*)d_in[1];
    const float* delta     = (const float*)d_in[2];
    const float* Wq  = (const float*)d_in[3];
    const float* bq  = (const float*)d_in[4];
    const float* Wk  = (const float*)d_in[5];
    const float* bk  = (const float*)d_in[6];
    const float* Wv  = (const float*)d_in[7];
    const float* bv  = (const float*)d_in[8];
    const float* Wfx = (const float*)d_in[9];
    const float* Wfy = (const float*)d_in[10];
    const float* Wfz = (const float*)d_in[11];
    float* out = (float*)d_out;

    prep_a_kernel<<<(ROWS * EDIM / 4) / 256, 256>>>(feats);
    prep_w_kernel<<<dim3(EDIM / 32, EDIM / 32, 3), 256>>>(Wq, Wk, Wv);

    cudaFuncSetAttribute(qkv_mma_kernel, cudaFuncAttributeMaxDynamicSharedMemorySize, GEMM_SMEM);
    dim3 gg(QKVN / 128, ROWS / 128);   // (18, 64)
    qkv_mma_kernel<<<gg, 256, GEMM_SMEM>>>(bq, bk, bv);

    vproj_kernel<<<ROWS / 8, 256>>>(Wfx, Wfy, Wfz);

    cudaFuncSetAttribute(attn_kernel, cudaFuncAttributeMaxDynamicSharedMemorySize, ATTN_SMEM);
    dim3 g2(SDIM / 16, BDIM);          // (16, 32)
    attn_kernel<<<g2, 256, ATTN_SMEM>>>(attn_bias, delta, out);
}

// round 12
// speedup vs baseline: 1.4621x; 1.2466x over previous
#include <cuda_runtime.h>
#include <cuda_fp16.h>
#include <cstdint>
#include <math.h>

#define BDIM 32
#define SDIM 256
#define EDIM 768
#define HDIM 32
#define DDIM 24
#define ROWS (BDIM*SDIM)     /* 8192 */
#define QKVN (3*EDIM)        /* 2304 */

// ---------------- device scratch (all fp16 path) ----------------
__device__ __align__(16) __half g_a_hi[(size_t)ROWS * EDIM];
__device__ __align__(16) __half g_b_hi[(size_t)QKVN * EDIM];   // wt[n][k]
__device__ __align__(16) __half g_b_lo[(size_t)QKVN * EDIM];
// q/k attn-ready packed fp16: [b][h][s][32] (cols 24..31 stay zero)
__device__ __align__(16) __half g_qh[(size_t)ROWS * HDIM * 32];
__device__ __align__(16) __half g_kh[(size_t)ROWS * HDIM * 32];
__device__ __align__(16) __half g_kl[(size_t)ROWS * HDIM * 32];
__device__ float g_v [(size_t)ROWS * EDIM];
__device__ float g_vp[(size_t)ROWS * HDIM * 4];

// ---------------- PTX helpers (base sm_80+ ISA only) ----------------
__device__ __forceinline__ uint32_t smem_to_u32(const void* p) {
    uint32_t a;
    asm("{ .reg .u64 t; cvta.to.shared.u64 t, %1; cvt.u32.u64 %0, t; }" : "=r"(a) : "l"(p));
    return a;
}
__device__ __forceinline__ void cp_async16(uint32_t s, const void* g) {
    asm volatile("cp.async.cg.shared.global [%0], [%1], 16;" :: "r"(s), "l"(g) : "memory");
}
__device__ __forceinline__ void ldsm4(uint32_t* r, uint32_t addr) {
    asm volatile("ldmatrix.sync.aligned.m8n8.x4.shared.b16 {%0,%1,%2,%3}, [%4];"
                 : "=r"(r[0]), "=r"(r[1]), "=r"(r[2]), "=r"(r[3]) : "r"(addr));
}
__device__ __forceinline__ void mma16816(float* c, const uint32_t* a, const uint32_t* b) {
    asm volatile("mma.sync.aligned.m16n8k16.row.col.f32.f16.f16.f32 "
                 "{%0,%1,%2,%3}, {%4,%5,%6,%7}, {%8,%9}, {%0,%1,%2,%3};"
                 : "+f"(c[0]), "+f"(c[1]), "+f"(c[2]), "+f"(c[3])
                 : "r"(a[0]), "r"(a[1]), "r"(a[2]), "r"(a[3]), "r"(b[0]), "r"(b[1]));
}

// ---------------- prep: feats -> fp16 ----------------
__global__ __launch_bounds__(256) void prep_a_kernel(const float* __restrict__ feats)
{
    const size_t i = (size_t)blockIdx.x * 256 + threadIdx.x;
    float4 v = ((const float4*)feats)[i];
    __half2* ph = (__half2*)g_a_hi;
    ph[2*i]   = __floats2half2_rn(v.x, v.y);
    ph[2*i+1] = __floats2half2_rn(v.z, v.w);
}

// ---------------- prep: weights transpose + fp16 hi/lo split ----------------
__global__ __launch_bounds__(256) void prep_w_kernel(
    const float* __restrict__ Wq, const float* __restrict__ Wk, const float* __restrict__ Wv)
{
    __shared__ float tile[32][33];
    const int which = blockIdx.z;
    const float* W = (which == 0) ? Wq : ((which == 1) ? Wk : Wv);
    const int n0 = blockIdx.x * 32, k0 = blockIdx.y * 32;
    const int tx = threadIdx.x & 31, ty = (threadIdx.x >> 5) * 4;
    #pragma unroll
    for (int i = 0; i < 4; i++)
        tile[ty + i][tx] = W[(size_t)(k0 + ty + i) * EDIM + n0 + tx];
    __syncthreads();
    #pragma unroll
    for (int i = 0; i < 4; i++) {
        const int n = n0 + ty + i, k = k0 + tx;
        const float v = tile[tx][ty + i];
        __half h = __float2half_rn(v);
        __half l = __float2half_rn(v - __half2float(h));
        g_b_hi[(size_t)(which * EDIM + n) * EDIM + k] = h;
        g_b_lo[(size_t)(which * EDIM + n) * EDIM + k] = l;
    }
}

// ---------------- HMMA QKV GEMM: 128x128, 256 thr, 3-stage, 2-pass fp16 ----------------
#define OFF_AHI 0
#define OFF_BHI 8192
#define OFF_BLO 16384
#define STG 24576
#define GEMM_SMEM (3*STG)
#define NCHUNK (EDIM/32)

__device__ __forceinline__ uint32_t sw_addr(uint32_t tile, int row, int kc) {
    return tile + (row << 6) + ((kc ^ ((row >> 1) & 3)) << 4);
}

__global__ __launch_bounds__(256, 2) void qkv_mma_kernel(
    const float* __restrict__ bq, const float* __restrict__ bk, const float* __restrict__ bv)
{
    extern __shared__ char smem[];
    const uint32_t smem_base = smem_to_u32(smem);
    const int tid  = threadIdx.x;
    const int wid  = tid >> 5;
    const int lane = tid & 31;
    const int m0    = blockIdx.y * 128;
    const int nbase = blockIdx.x * 128;

    const int wm = wid & 1, wn = wid >> 1;
    const int mw = wm * 64, nw = wn * 32;
    const int lane7 = lane & 7, quad = lane >> 3;

    float c[4][4][4];
    #pragma unroll
    for (int i = 0; i < 4; i++)
        #pragma unroll
        for (int j = 0; j < 4; j++)
            #pragma unroll
            for (int r = 0; r < 4; r++) c[i][j][r] = 0.f;

    auto copy_stage = [&](int s) {
        const uint32_t sb = smem_base + (s % 3) * STG;
        const int k0 = s * 32;
        #pragma unroll
        for (int i = 0; i < 2; i++) {
            const int idx = tid + i * 256;
            const int row = idx >> 2, cc = idx & 3;
            const uint32_t soff = (row << 6) + ((cc ^ ((row >> 1) & 3)) << 4);
            const size_t ga = (size_t)(m0 + row) * EDIM + k0 + cc * 8;
            const size_t gb = (size_t)(nbase + row) * EDIM + k0 + cc * 8;
            cp_async16(sb + OFF_AHI + soff, g_a_hi + ga);
            cp_async16(sb + OFF_BHI + soff, g_b_hi + gb);
            cp_async16(sb + OFF_BLO + soff, g_b_lo + gb);
        }
        asm volatile("cp.async.commit_group;" ::: "memory");
    };

    copy_stage(0);
    copy_stage(1);

    for (int ch = 0; ch < NCHUNK; ch++) {
        if (ch + 1 < NCHUNK) {
            asm volatile("cp.async.wait_group 1;" ::: "memory");
        } else {
            asm volatile("cp.async.wait_group 0;" ::: "memory");
        }
        __syncthreads();
        if (ch + 2 < NCHUNK) copy_stage(ch + 2);

        const uint32_t sb = smem_base + (ch % 3) * STG;
        #pragma unroll
        for (int ks = 0; ks < 2; ks++) {
            uint32_t bh[4][2], bl[4][2], a[4][4];
            #pragma unroll
            for (int j2 = 0; j2 < 2; j2++) {
                const int rowB = nw + j2 * 16 + ((quad >> 1) << 3) + lane7;
                const int kcB  = 2 * ks + (quad & 1);
                uint32_t r[4];
                ldsm4(r, sw_addr(sb + OFF_BHI, rowB, kcB));
                bh[2*j2][0] = r[0]; bh[2*j2][1] = r[1];
                bh[2*j2+1][0] = r[2]; bh[2*j2+1][1] = r[3];
                ldsm4(r, sw_addr(sb + OFF_BLO, rowB, kcB));
                bl[2*j2][0] = r[0]; bl[2*j2][1] = r[1];
                bl[2*j2+1][0] = r[2]; bl[2*j2+1][1] = r[3];
            }
            const int rowA_ = ((quad & 1) << 3) + lane7;
            const int kcA   = 2 * ks + (quad >> 1);
            #pragma unroll
            for (int i = 0; i < 4; i++)
                ldsm4(a[i], sw_addr(sb + OFF_AHI, mw + 16 * i + rowA_, kcA));
            #pragma unroll
            for (int i = 0; i < 4; i++)
                #pragma unroll
                for (int j = 0; j < 4; j++) {
                    mma16816(c[i][j], a[i], bh[j]);   // Ahi * Bhi
                    mma16816(c[i][j], a[i], bl[j]);   // Ahi * Blo
                }
        }
        __syncthreads();
    }

    // ---- epilogue ----
    const int which = blockIdx.x / 6;
    const int ncol_off = which * EDIM;
    const float* bias = (which == 0) ? bq : ((which == 1) ? bk : bv);
    const float scale = (which == 0) ? 0.20412414523193154f : 1.0f;
    const int g  = lane >> 2;
    const int t4 = lane & 3;

    #pragma unroll
    for (int i = 0; i < 4; i++) {
        #pragma unroll
        for (int half = 0; half < 2; half++) {
            const int row = m0 + mw + 16 * i + g + 8 * half;
            const int bb = row >> 8, tt = row & 255;
            #pragma unroll
            for (int j = 0; j < 4; j++) {
                const int col = nbase + nw + 8 * j + 2 * t4 - ncol_off;
                float2 v;
                v.x = (c[i][j][2*half + 0] + bias[col])     * scale;
                v.y = (c[i][j][2*half + 1] + bias[col + 1]) * scale;
                if (which == 2) {
                    *(float2*)&g_v[(size_t)row * EDIM + col] = v;
                } else {
                    const int h = col / DDIM, d = col - h * DDIM;
                    const size_t off = ((size_t)(bb * HDIM + h) * SDIM + tt) * 32 + d;
                    __half2 hv = __floats2half2_rn(v.x, v.y);
                    if (which == 0) {
                        *(__half2*)&g_qh[off] = hv;
                    } else {
                        *(__half2*)&g_kh[off] = hv;
                        __half2 lv = __floats2half2_rn(v.x - __half2float(__low2half(hv)),
                                                       v.y - __half2float(__high2half(hv)));
                        *(__half2*)&g_kl[off] = lv;
                    }
                }
            }
        }
    }
}

// ---------------- vproj ----------------
__global__ __launch_bounds__(256) void vproj_kernel(
    const float* __restrict__ Wfx, const float* __restrict__ Wfy, const float* __restrict__ Wfz)
{
    const int row = blockIdx.x * 8 + (threadIdx.x >> 5);
    const int h   = threadIdx.x & 31;
    const float* v  = g_v + (size_t)row * EDIM + h * DDIM;
    const float* wx = Wfx + h * DDIM;
    const float* wy = Wfy + h * DDIM;
    const float* wz = Wfz + h * DDIM;
    float vx = 0.f, vy = 0.f, vz = 0.f;
    #pragma unroll
    for (int i = 0; i < 6; i++) {
        float4 vv = *(const float4*)(v  + 4 * i);
        float4 ax = *(const float4*)(wx + 4 * i);
        float4 ay = *(const float4*)(wy + 4 * i);
        float4 az = *(const float4*)(wz + 4 * i);
        vx += vv.x*ax.x + vv.y*ax.y + vv.z*ax.z + vv.w*ax.w;
        vy += vv.x*ay.x + vv.y*ay.y + vv.z*ay.z + vv.w*ay.w;
        vz += vv.x*az.x + vv.y*az.y + vv.z*az.z + vv.w*az.w;
    }
    const int b = row >> 8, t = row & 255;
    *(float4*)&g_vp[((size_t)(b * HDIM + h) * SDIM + t) * 4] = make_float4(vx, vy, vz, 0.f);
}

// ---------------- MMA attention: fp16, 4 MMAs/j, 16 s-rows, 2 blocks/SM ----------------
#define AKH   0
#define AKL   16384
#define AVP   32768
#define ABIA  36864
#define BROW  1040
#define ASTG  53504
#define AZP   (2*ASTG)
#define ARED  (2*ASTG + 1024)
#define ATTN_SMEM (2*ASTG + 1024 + 1536)

__global__ __launch_bounds__(256, 2) void attn_kernel(
    const float* __restrict__ attn_bias,
    const float* __restrict__ delta,
    float* __restrict__ out)
{
    extern __shared__ char sa[];
    const uint32_t sb = smem_to_u32(sa);
    const int b   = blockIdx.y;
    const int s0  = blockIdx.x * 16;
    const int tid = threadIdx.x;
    const int lane = tid & 31;
    const int band = tid >> 5;
    const int nb   = band * 32;
    const int g    = lane >> 2;
    const int t4   = lane & 3;
    const int l8   = lane & 7, l8h = lane >> 3;

    auto stage = [&](int hh) {
        const uint32_t bufs = sb + (hh & 1) * ASTG;
        const size_t kbase = (size_t)(b * HDIM + hh) * SDIM * 32;
        #pragma unroll
        for (int i = 0; i < 4; i++) {
            const int m = tid + i * 256;
            const int r = m >> 2, c2 = m & 3;
            const uint32_t so = (r << 6) + ((c2 ^ ((r >> 1) & 3)) << 4);
            cp_async16(bufs + AKH + so, g_kh + kbase + r * 32 + c2 * 8);
            cp_async16(bufs + AKL + so, g_kl + kbase + r * 32 + c2 * 8);
        }
        cp_async16(bufs + AVP + tid * 16,
                   g_vp + (size_t)(b * HDIM + hh) * SDIM * 4 + tid * 4);
        const float* bsrc = attn_bias + (((size_t)b * HDIM + hh) * SDIM + s0) * SDIM;
        #pragma unroll
        for (int i = 0; i < 4; i++) {
            const int m = tid + i * 256;
            const int r = m >> 6, cc = m & 63;
            cp_async16(bufs + ABIA + r * BROW + cc * 16, bsrc + (size_t)r * SDIM + cc * 4);
        }
        asm volatile("cp.async.commit_group;" ::: "memory");
    };

    float G[2][4][2][3];
    #pragma unroll
    for (int r = 0; r < 2; r++)
        #pragma unroll
        for (int j = 0; j < 4; j++)
            #pragma unroll
            for (int cc = 0; cc < 2; cc++)
                #pragma unroll
                for (int x = 0; x < 3; x++) G[r][j][cc][x] = 0.f;

    stage(0);

    for (int h = 0; h < HDIM; h++) {
        const int par = h & 1;
        asm volatile("cp.async.wait_group 0;" ::: "memory");
        __syncthreads();
        if (h + 1 < HDIM) stage(h + 1);

        // q fragments direct from gmem (packed fp16, pad cols zero)
        const size_t qoff = ((size_t)(b * HDIM + h) * SDIM + s0) * 32;
        const __half* qh = g_qh + qoff;
        uint32_t ah[2][4];
        #pragma unroll
        for (int kk = 0; kk < 2; kk++) {
            const int kb = 16 * kk + 2 * t4;
            ah[kk][0] = *(const uint32_t*)&qh[(g)     * 32 + kb];
            ah[kk][1] = *(const uint32_t*)&qh[(g + 8) * 32 + kb];
            ah[kk][2] = *(const uint32_t*)&qh[(g)     * 32 + kb + 8];
            ah[kk][3] = *(const uint32_t*)&qh[(g + 8) * 32 + kb + 8];
        }

        const uint32_t bufs = sb + par * ASTG;

        float c[4][4];
        #pragma unroll
        for (int j = 0; j < 4; j++)
            #pragma unroll
            for (int r = 0; r < 4; r++) c[j][r] = 0.f;

        #pragma unroll
        for (int j = 0; j < 4; j++) {
            uint32_t bh[4], bl[4];
            const int rowB = nb + j * 8 + l8;
            const uint32_t so = (rowB << 6) + ((l8h ^ ((rowB >> 1) & 3)) << 4);
            ldsm4(bh, bufs + AKH + so);
            ldsm4(bl, bufs + AKL + so);
            mma16816(c[j], ah[0], bh);       // qhi * khi
            mma16816(c[j], ah[1], bh + 2);
            mma16816(c[j], ah[0], bl);       // qhi * klo
            mma16816(c[j], ah[1], bl + 2);
        }

        const char* bp0 = sa + par * ASTG + ABIA + g * BROW + (nb + 2 * t4) * 4;
        const char* bp1 = bp0 + 8 * BROW;
        float ps0 = 0.f, ps1 = 0.f;
        #pragma unroll
        for (int j = 0; j < 4; j++) {
            float2 b0 = *(const float2*)(bp0 + 32 * j);
            float2 b1 = *(const float2*)(bp1 + 32 * j);
            c[j][0] = __expf(c[j][0] + b0.x);
            c[j][1] = __expf(c[j][1] + b0.y);
            c[j][2] = __expf(c[j][2] + b1.x);
            c[j][3] = __expf(c[j][3] + b1.y);
            ps0 += c[j][0] + c[j][1];
            ps1 += c[j][2] + c[j][3];
        }
        ps0 += __shfl_xor_sync(0xffffffffu, ps0, 1);
        ps0 += __shfl_xor_sync(0xffffffffu, ps0, 2);
        ps1 += __shfl_xor_sync(0xffffffffu, ps1, 1);
        ps1 += __shfl_xor_sync(0xffffffffu, ps1, 2);
        float* zp = (float*)(sa + AZP + par * 512);
        if (t4 == 0) {
            zp[(g)     * 8 + band] = ps0;
            zp[(g + 8) * 8 + band] = ps1;
        }
        __syncthreads();

        float Z0, Z1;
        {
            float4 a0 = *(float4*)(zp + g * 8);
            float4 a1 = *(float4*)(zp + g * 8 + 4);
            Z0 = (a0.x + a0.y) + (a0.z + a0.w) + (a1.x + a1.y) + (a1.z + a1.w);
            float4 b0 = *(float4*)(zp + (g + 8) * 8);
            float4 b1 = *(float4*)(zp + (g + 8) * 8 + 4);
            Z1 = (b0.x + b0.y) + (b0.z + b0.w) + (b1.x + b1.y) + (b1.z + b1.w);
        }
        const float iz0 = __fdividef(1.f, Z0);
        const float iz1 = __fdividef(1.f, Z1);

        #pragma unroll
        for (int j = 0; j < 4; j++) {
            const char* vpp = sa + par * ASTG + AVP + (nb + 8 * j + 2 * t4) * 16;
            float4 v0 = *(const float4*)vpp;
            float4 v1 = *(const float4*)(vpp + 16);
            const float p00 = c[j][0] * iz0, p01 = c[j][1] * iz0;
            const float p10 = c[j][2] * iz1, p11 = c[j][3] * iz1;
            G[0][j][0][0] = fmaf(p00, v0.x, G[0][j][0][0]);
            G[0][j][0][1] = fmaf(p00, v0.y, G[0][j][0][1]);
            G[0][j][0][2] = fmaf(p00, v0.z, G[0][j][0][2]);
            G[0][j][1][0] = fmaf(p01, v1.x, G[0][j][1][0]);
            G[0][j][1][1] = fmaf(p01, v1.y, G[0][j][1][1]);
            G[0][j][1][2] = fmaf(p01, v1.z, G[0][j][1][2]);
            G[1][j][0][0] = fmaf(p10, v0.x, G[1][j][0][0]);
            G[1][j][0][1] = fmaf(p10, v0.y, G[1][j][0][1]);
            G[1][j][0][2] = fmaf(p10, v0.z, G[1][j][0][2]);
            G[1][j][1][0] = fmaf(p11, v1.x, G[1][j][1][0]);
            G[1][j][1][1] = fmaf(p11, v1.y, G[1][j][1][1]);
            G[1][j][1][2] = fmaf(p11, v1.z, G[1][j][1][2]);
        }
    }

    // ---- delta contraction + output ----
    float ox[2] = {0.f, 0.f}, oy[2] = {0.f, 0.f}, oz[2] = {0.f, 0.f};
    #pragma unroll
    for (int rh = 0; rh < 2; rh++) {
        const int srow = s0 + g + 8 * rh;
        const float* dp = delta + (size_t)(b * SDIM + srow) * SDIM * 3;
        #pragma unroll
        for (int j = 0; j < 4; j++) {
            const int t0 = nb + 8 * j + 2 * t4;
            const float* d0 = dp + t0 * 3;
            ox[rh] += G[rh][j][0][0] * d0[0] + G[rh][j][1][0] * d0[3];
            oy[rh] += G[rh][j][0][1] * d0[1] + G[rh][j][1][1] * d0[4];
            oz[rh] += G[rh][j][0][2] * d0[2] + G[rh][j][1][2] * d0[5];
        }
    }
    #pragma unroll
    for (int rh = 0; rh < 2; rh++) {
        ox[rh] += __shfl_xor_sync(0xffffffffu, ox[rh], 1);
        ox[rh] += __shfl_xor_sync(0xffffffffu, ox[rh], 2);
        oy[rh] += __shfl_xor_sync(0xffffffffu, oy[rh], 1);
        oy[rh] += __shfl_xor_sync(0xffffffffu, oy[rh], 2);
        oz[rh] += __shfl_xor_sync(0xffffffffu, oz[rh], 1);
        oz[rh] += __shfl_xor_sync(0xffffffffu, oz[rh], 2);
    }
    float* red = (float*)(sa + ARED);
    if (t4 == 0) {
        #pragma unroll
        for (int rh = 0; rh < 2; rh++) {
            const int row = g + 8 * rh;
            red[(row * 8 + band) * 3 + 0] = ox[rh];
            red[(row * 8 + band) * 3 + 1] = oy[rh];
            red[(row * 8 + band) * 3 + 2] = oz[rh];
        }
    }
    __syncthreads();
    if (tid < 48) {
        const int row = tid / 3, x = tid % 3;
        float s = 0.f;
        #pragma unroll
        for (int k = 0; k < 8; k++) s += red[(row * 8 + k) * 3 + x];
        out[((size_t)(b * SDIM) + s0 + row) * 3 + x] = s;
    }
}

// ---------------- launch ----------------
extern "C" void kernel_launch(void* const* d_in, const int* in_sizes, int n_in,
                              void* d_out, int out_size)
{
    const float* feats     = (const float*)d_in[0];
    const float* attn_bias = (const float*)d_in[1];
    const float* delta     = (const float*)d_in[2];
    const float* Wq  = (const float*)d_in[3];
    const float* bq  = (const float*)d_in[4];
    const float* Wk  = (const float*)d_in[5];
    const float* bk  = (const float*)d_in[6];
    const float* Wv  = (const float*)d_in[7];
    const float* bv  = (const float*)d_in[8];
    const float* Wfx = (const float*)d_in[9];
    const float* Wfy = (const float*)d_in[10];
    const float* Wfz = (const float*)d_in[11];
    float* out = (float*)d_out;

    prep_a_kernel<<<(ROWS * EDIM / 4) / 256, 256>>>(feats);
    prep_w_kernel<<<dim3(EDIM / 32, EDIM / 32, 3), 256>>>(Wq, Wk, Wv);

    cudaFuncSetAttribute(qkv_mma_kernel, cudaFuncAttributeMaxDynamicSharedMemorySize, GEMM_SMEM);
    dim3 gg(QKVN / 128, ROWS / 128);   // (18, 64)
    qkv_mma_kernel<<<gg, 256, GEMM_SMEM>>>(bq, bk, bv);

    vproj_kernel<<<ROWS / 8, 256>>>(Wfx, Wfy, Wfz);

    cudaFuncSetAttribute(attn_kernel, cudaFuncAttributeMaxDynamicSharedMemorySize, ATTN_SMEM);
    dim3 g2(SDIM / 16, BDIM);          // (16, 32)
    attn_kernel<<<g2, 256, ATTN_SMEM>>>(attn_bias, delta, out);
}

// round 13
// speedup vs baseline: 1.8376x; 1.2568x over previous
#include <cuda_runtime.h>
#include <cuda_fp16.h>
#include <cstdint>
#include <math.h>

#define BDIM 32
#define SDIM 256
#define EDIM 768
#define HDIM 32
#define DDIM 24
#define ROWS (BDIM*SDIM)     /* 8192 */
#define QKVN (3*EDIM)        /* 2304 */

// ---------------- device scratch (all fp16 path) ----------------
__device__ __align__(16) __half g_a_hi[(size_t)ROWS * EDIM];
__device__ __align__(16) __half g_b_hi[(size_t)QKVN * EDIM];   // wt[n][k]
// q/k attn-ready packed fp16: [b][h][s][32] (cols 24..31 stay zero)
__device__ __align__(16) __half g_qh[(size_t)ROWS * HDIM * 32];
__device__ __align__(16) __half g_kh[(size_t)ROWS * HDIM * 32];
__device__ __align__(16) __half g_kl[(size_t)ROWS * HDIM * 32];
__device__ float g_v [(size_t)ROWS * EDIM];
__device__ float g_vp[(size_t)ROWS * HDIM * 4];

// ---------------- PTX helpers (base sm_80+ ISA only) ----------------
__device__ __forceinline__ uint32_t smem_to_u32(const void* p) {
    uint32_t a;
    asm("{ .reg .u64 t; cvta.to.shared.u64 t, %1; cvt.u32.u64 %0, t; }" : "=r"(a) : "l"(p));
    return a;
}
__device__ __forceinline__ void cp_async16(uint32_t s, const void* g) {
    asm volatile("cp.async.cg.shared.global [%0], [%1], 16;" :: "r"(s), "l"(g) : "memory");
}
__device__ __forceinline__ void ldsm4(uint32_t* r, uint32_t addr) {
    asm volatile("ldmatrix.sync.aligned.m8n8.x4.shared.b16 {%0,%1,%2,%3}, [%4];"
                 : "=r"(r[0]), "=r"(r[1]), "=r"(r[2]), "=r"(r[3]) : "r"(addr));
}
__device__ __forceinline__ void mma16816(float* c, const uint32_t* a, const uint32_t* b) {
    asm volatile("mma.sync.aligned.m16n8k16.row.col.f32.f16.f16.f32 "
                 "{%0,%1,%2,%3}, {%4,%5,%6,%7}, {%8,%9}, {%0,%1,%2,%3};"
                 : "+f"(c[0]), "+f"(c[1]), "+f"(c[2]), "+f"(c[3])
                 : "r"(a[0]), "r"(a[1]), "r"(a[2]), "r"(a[3]), "r"(b[0]), "r"(b[1]));
}

// ---------------- prep: feats -> fp16 ----------------
__global__ __launch_bounds__(256) void prep_a_kernel(const float* __restrict__ feats)
{
    const size_t i = (size_t)blockIdx.x * 256 + threadIdx.x;
    float4 v = ((const float4*)feats)[i];
    __half2* ph = (__half2*)g_a_hi;
    ph[2*i]   = __floats2half2_rn(v.x, v.y);
    ph[2*i+1] = __floats2half2_rn(v.z, v.w);
}

// ---------------- prep: weights transpose -> fp16 ----------------
__global__ __launch_bounds__(256) void prep_w_kernel(
    const float* __restrict__ Wq, const float* __restrict__ Wk, const float* __restrict__ Wv)
{
    __shared__ float tile[32][33];
    const int which = blockIdx.z;
    const float* W = (which == 0) ? Wq : ((which == 1) ? Wk : Wv);
    const int n0 = blockIdx.x * 32, k0 = blockIdx.y * 32;
    const int tx = threadIdx.x & 31, ty = (threadIdx.x >> 5) * 4;
    #pragma unroll
    for (int i = 0; i < 4; i++)
        tile[ty + i][tx] = W[(size_t)(k0 + ty + i) * EDIM + n0 + tx];
    __syncthreads();
    #pragma unroll
    for (int i = 0; i < 4; i++) {
        const int n = n0 + ty + i, k = k0 + tx;
        g_b_hi[(size_t)(which * EDIM + n) * EDIM + k] = __float2half_rn(tile[tx][ty + i]);
    }
}

// ---------------- HMMA QKV GEMM: 128x128, 256 thr, 3-stage, single-pass fp16 ----------------
#define OFF_AHI 0
#define OFF_BHI 8192
#define STG 16384
#define GEMM_SMEM (3*STG)
#define NCHUNK (EDIM/32)

__device__ __forceinline__ uint32_t sw_addr(uint32_t tile, int row, int kc) {
    return tile + (row << 6) + ((kc ^ ((row >> 1) & 3)) << 4);
}

__global__ __launch_bounds__(256, 2) void qkv_mma_kernel(
    const float* __restrict__ bq, const float* __restrict__ bk, const float* __restrict__ bv)
{
    extern __shared__ char smem[];
    const uint32_t smem_base = smem_to_u32(smem);
    const int tid  = threadIdx.x;
    const int wid  = tid >> 5;
    const int lane = tid & 31;
    const int m0    = blockIdx.y * 128;
    const int nbase = blockIdx.x * 128;

    const int wm = wid & 1, wn = wid >> 1;
    const int mw = wm * 64, nw = wn * 32;
    const int lane7 = lane & 7, quad = lane >> 3;

    float c[4][4][4];
    #pragma unroll
    for (int i = 0; i < 4; i++)
        #pragma unroll
        for (int j = 0; j < 4; j++)
            #pragma unroll
            for (int r = 0; r < 4; r++) c[i][j][r] = 0.f;

    auto copy_stage = [&](int s) {
        const uint32_t sb = smem_base + (s % 3) * STG;
        const int k0 = s * 32;
        #pragma unroll
        for (int i = 0; i < 2; i++) {
            const int idx = tid + i * 256;
            const int row = idx >> 2, cc = idx & 3;
            const uint32_t soff = (row << 6) + ((cc ^ ((row >> 1) & 3)) << 4);
            const size_t ga = (size_t)(m0 + row) * EDIM + k0 + cc * 8;
            const size_t gb = (size_t)(nbase + row) * EDIM + k0 + cc * 8;
            cp_async16(sb + OFF_AHI + soff, g_a_hi + ga);
            cp_async16(sb + OFF_BHI + soff, g_b_hi + gb);
        }
        asm volatile("cp.async.commit_group;" ::: "memory");
    };

    copy_stage(0);
    copy_stage(1);

    for (int ch = 0; ch < NCHUNK; ch++) {
        if (ch + 1 < NCHUNK) {
            asm volatile("cp.async.wait_group 1;" ::: "memory");
        } else {
            asm volatile("cp.async.wait_group 0;" ::: "memory");
        }
        __syncthreads();
        if (ch + 2 < NCHUNK) copy_stage(ch + 2);

        const uint32_t sb = smem_base + (ch % 3) * STG;
        #pragma unroll
        for (int ks = 0; ks < 2; ks++) {
            uint32_t bh[4][2], a[4][4];
            #pragma unroll
            for (int j2 = 0; j2 < 2; j2++) {
                const int rowB = nw + j2 * 16 + ((quad >> 1) << 3) + lane7;
                const int kcB  = 2 * ks + (quad & 1);
                uint32_t r[4];
                ldsm4(r, sw_addr(sb + OFF_BHI, rowB, kcB));
                bh[2*j2][0] = r[0]; bh[2*j2][1] = r[1];
                bh[2*j2+1][0] = r[2]; bh[2*j2+1][1] = r[3];
            }
            const int rowA_ = ((quad & 1) << 3) + lane7;
            const int kcA   = 2 * ks + (quad >> 1);
            #pragma unroll
            for (int i = 0; i < 4; i++)
                ldsm4(a[i], sw_addr(sb + OFF_AHI, mw + 16 * i + rowA_, kcA));
            #pragma unroll
            for (int i = 0; i < 4; i++)
                #pragma unroll
                for (int j = 0; j < 4; j++)
                    mma16816(c[i][j], a[i], bh[j]);
        }
        __syncthreads();
    }

    // ---- epilogue ----
    const int which = blockIdx.x / 6;
    const int ncol_off = which * EDIM;
    const float* bias = (which == 0) ? bq : ((which == 1) ? bk : bv);
    const float scale = (which == 0) ? 0.20412414523193154f : 1.0f;
    const int g  = lane >> 2;
    const int t4 = lane & 3;

    #pragma unroll
    for (int i = 0; i < 4; i++) {
        #pragma unroll
        for (int half = 0; half < 2; half++) {
            const int row = m0 + mw + 16 * i + g + 8 * half;
            const int bb = row >> 8, tt = row & 255;
            #pragma unroll
            for (int j = 0; j < 4; j++) {
                const int col = nbase + nw + 8 * j + 2 * t4 - ncol_off;
                float2 v;
                v.x = (c[i][j][2*half + 0] + bias[col])     * scale;
                v.y = (c[i][j][2*half + 1] + bias[col + 1]) * scale;
                if (which == 2) {
                    *(float2*)&g_v[(size_t)row * EDIM + col] = v;
                } else {
                    const int h = col / DDIM, d = col - h * DDIM;
                    const size_t off = ((size_t)(bb * HDIM + h) * SDIM + tt) * 32 + d;
                    __half2 hv = __floats2half2_rn(v.x, v.y);
                    if (which == 0) {
                        *(__half2*)&g_qh[off] = hv;
                    } else {
                        *(__half2*)&g_kh[off] = hv;
                        __half2 lv = __floats2half2_rn(v.x - __half2float(__low2half(hv)),
                                                       v.y - __half2float(__high2half(hv)));
                        *(__half2*)&g_kl[off] = lv;
                    }
                }
            }
        }
    }
}

// ---------------- vproj ----------------
__global__ __launch_bounds__(256) void vproj_kernel(
    const float* __restrict__ Wfx, const float* __restrict__ Wfy, const float* __restrict__ Wfz)
{
    const int row = blockIdx.x * 8 + (threadIdx.x >> 5);
    const int h   = threadIdx.x & 31;
    const float* v  = g_v + (size_t)row * EDIM + h * DDIM;
    const float* wx = Wfx + h * DDIM;
    const float* wy = Wfy + h * DDIM;
    const float* wz = Wfz + h * DDIM;
    float vx = 0.f, vy = 0.f, vz = 0.f;
    #pragma unroll
    for (int i = 0; i < 6; i++) {
        float4 vv = *(const float4*)(v  + 4 * i);
        float4 ax = *(const float4*)(wx + 4 * i);
        float4 ay = *(const float4*)(wy + 4 * i);
        float4 az = *(const float4*)(wz + 4 * i);
        vx += vv.x*ax.x + vv.y*ax.y + vv.z*ax.z + vv.w*ax.w;
        vy += vv.x*ay.x + vv.y*ay.y + vv.z*ay.z + vv.w*ay.w;
        vz += vv.x*az.x + vv.y*az.y + vv.z*az.z + vv.w*az.w;
    }
    const int b = row >> 8, t = row & 255;
    *(float4*)&g_vp[((size_t)(b * HDIM + h) * SDIM + t) * 4] = make_float4(vx, vy, vz, 0.f);
}

// ---------------- MMA attention: fp16, 4 MMAs/j, 16 s-rows, 2 blocks/SM ----------------
#define AKH   0
#define AKL   16384
#define AVP   32768
#define ABIA  36864
#define BROW  1040
#define ASTG  53504
#define AZP   (2*ASTG)
#define ARED  (2*ASTG + 1024)
#define ATTN_SMEM (2*ASTG + 1024 + 1536)

__global__ __launch_bounds__(256, 2) void attn_kernel(
    const float* __restrict__ attn_bias,
    const float* __restrict__ delta,
    float* __restrict__ out)
{
    extern __shared__ char sa[];
    const uint32_t sb = smem_to_u32(sa);
    const int b   = blockIdx.y;
    const int s0  = blockIdx.x * 16;
    const int tid = threadIdx.x;
    const int lane = tid & 31;
    const int band = tid >> 5;
    const int nb   = band * 32;
    const int g    = lane >> 2;
    const int t4   = lane & 3;
    const int l8   = lane & 7, l8h = lane >> 3;

    auto stage = [&](int hh) {
        const uint32_t bufs = sb + (hh & 1) * ASTG;
        const size_t kbase = (size_t)(b * HDIM + hh) * SDIM * 32;
        #pragma unroll
        for (int i = 0; i < 4; i++) {
            const int m = tid + i * 256;
            const int r = m >> 2, c2 = m & 3;
            const uint32_t so = (r << 6) + ((c2 ^ ((r >> 1) & 3)) << 4);
            cp_async16(bufs + AKH + so, g_kh + kbase + r * 32 + c2 * 8);
            cp_async16(bufs + AKL + so, g_kl + kbase + r * 32 + c2 * 8);
        }
        cp_async16(bufs + AVP + tid * 16,
                   g_vp + (size_t)(b * HDIM + hh) * SDIM * 4 + tid * 4);
        const float* bsrc = attn_bias + (((size_t)b * HDIM + hh) * SDIM + s0) * SDIM;
        #pragma unroll
        for (int i = 0; i < 4; i++) {
            const int m = tid + i * 256;
            const int r = m >> 6, cc = m & 63;
            cp_async16(bufs + ABIA + r * BROW + cc * 16, bsrc + (size_t)r * SDIM + cc * 4);
        }
        asm volatile("cp.async.commit_group;" ::: "memory");
    };

    float G[2][4][2][3];
    #pragma unroll
    for (int r = 0; r < 2; r++)
        #pragma unroll
        for (int j = 0; j < 4; j++)
            #pragma unroll
            for (int cc = 0; cc < 2; cc++)
                #pragma unroll
                for (int x = 0; x < 3; x++) G[r][j][cc][x] = 0.f;

    stage(0);

    for (int h = 0; h < HDIM; h++) {
        const int par = h & 1;
        asm volatile("cp.async.wait_group 0;" ::: "memory");
        __syncthreads();
        if (h + 1 < HDIM) stage(h + 1);

        const size_t qoff = ((size_t)(b * HDIM + h) * SDIM + s0) * 32;
        const __half* qh = g_qh + qoff;
        uint32_t ah[2][4];
        #pragma unroll
        for (int kk = 0; kk < 2; kk++) {
            const int kb = 16 * kk + 2 * t4;
            ah[kk][0] = *(const uint32_t*)&qh[(g)     * 32 + kb];
            ah[kk][1] = *(const uint32_t*)&qh[(g + 8) * 32 + kb];
            ah[kk][2] = *(const uint32_t*)&qh[(g)     * 32 + kb + 8];
            ah[kk][3] = *(const uint32_t*)&qh[(g + 8) * 32 + kb + 8];
        }

        const uint32_t bufs = sb + par * ASTG;

        float c[4][4];
        #pragma unroll
        for (int j = 0; j < 4; j++)
            #pragma unroll
            for (int r = 0; r < 4; r++) c[j][r] = 0.f;

        #pragma unroll
        for (int j = 0; j < 4; j++) {
            uint32_t bh[4], bl[4];
            const int rowB = nb + j * 8 + l8;
            const uint32_t so = (rowB << 6) + ((l8h ^ ((rowB >> 1) & 3)) << 4);
            ldsm4(bh, bufs + AKH + so);
            ldsm4(bl, bufs + AKL + so);
            mma16816(c[j], ah[0], bh);       // qhi * khi
            mma16816(c[j], ah[1], bh + 2);
            mma16816(c[j], ah[0], bl);       // qhi * klo
            mma16816(c[j], ah[1], bl + 2);
        }

        const char* bp0 = sa + par * ASTG + ABIA + g * BROW + (nb + 2 * t4) * 4;
        const char* bp1 = bp0 + 8 * BROW;
        float ps0 = 0.f, ps1 = 0.f;
        #pragma unroll
        for (int j = 0; j < 4; j++) {
            float2 b0 = *(const float2*)(bp0 + 32 * j);
            float2 b1 = *(const float2*)(bp1 + 32 * j);
            c[j][0] = __expf(c[j][0] + b0.x);
            c[j][1] = __expf(c[j][1] + b0.y);
            c[j][2] = __expf(c[j][2] + b1.x);
            c[j][3] = __expf(c[j][3] + b1.y);
            ps0 += c[j][0] + c[j][1];
            ps1 += c[j][2] + c[j][3];
        }
        ps0 += __shfl_xor_sync(0xffffffffu, ps0, 1);
        ps0 += __shfl_xor_sync(0xffffffffu, ps0, 2);
        ps1 += __shfl_xor_sync(0xffffffffu, ps1, 1);
        ps1 += __shfl_xor_sync(0xffffffffu, ps1, 2);
        float* zp = (float*)(sa + AZP + par * 512);
        if (t4 == 0) {
            zp[(g)     * 8 + band] = ps0;
            zp[(g + 8) * 8 + band] = ps1;
        }
        __syncthreads();

        float Z0, Z1;
        {
            float4 a0 = *(float4*)(zp + g * 8);
            float4 a1 = *(float4*)(zp + g * 8 + 4);
            Z0 = (a0.x + a0.y) + (a0.z + a0.w) + (a1.x + a1.y) + (a1.z + a1.w);
            float4 b0 = *(float4*)(zp + (g + 8) * 8);
            float4 b1 = *(float4*)(zp + (g + 8) * 8 + 4);
            Z1 = (b0.x + b0.y) + (b0.z + b0.w) + (b1.x + b1.y) + (b1.z + b1.w);
        }
        const float iz0 = __fdividef(1.f, Z0);
        const float iz1 = __fdividef(1.f, Z1);

        #pragma unroll
        for (int j = 0; j < 4; j++) {
            const char* vpp = sa + par * ASTG + AVP + (nb + 8 * j + 2 * t4) * 16;
            float4 v0 = *(const float4*)vpp;
            float4 v1 = *(const float4*)(vpp + 16);
            const float p00 = c[j][0] * iz0, p01 = c[j][1] * iz0;
            const float p10 = c[j][2] * iz1, p11 = c[j][3] * iz1;
            G[0][j][0][0] = fmaf(p00, v0.x, G[0][j][0][0]);
            G[0][j][0][1] = fmaf(p00, v0.y, G[0][j][0][1]);
            G[0][j][0][2] = fmaf(p00, v0.z, G[0][j][0][2]);
            G[0][j][1][0] = fmaf(p01, v1.x, G[0][j][1][0]);
            G[0][j][1][1] = fmaf(p01, v1.y, G[0][j][1][1]);
            G[0][j][1][2] = fmaf(p01, v1.z, G[0][j][1][2]);
            G[1][j][0][0] = fmaf(p10, v0.x, G[1][j][0][0]);
            G[1][j][0][1] = fmaf(p10, v0.y, G[1][j][0][1]);
            G[1][j][0][2] = fmaf(p10, v0.z, G[1][j][0][2]);
            G[1][j][1][0] = fmaf(p11, v1.x, G[1][j][1][0]);
            G[1][j][1][1] = fmaf(p11, v1.y, G[1][j][1][1]);
            G[1][j][1][2] = fmaf(p11, v1.z, G[1][j][1][2]);
        }
    }

    // ---- delta contraction + output ----
    float ox[2] = {0.f, 0.f}, oy[2] = {0.f, 0.f}, oz[2] = {0.f, 0.f};
    #pragma unroll
    for (int rh = 0; rh < 2; rh++) {
        const int srow = s0 + g + 8 * rh;
        const float* dp = delta + (size_t)(b * SDIM + srow) * SDIM * 3;
        #pragma unroll
        for (int j = 0; j < 4; j++) {
            const int t0 = nb + 8 * j + 2 * t4;
            const float* d0 = dp + t0 * 3;
            ox[rh] += G[rh][j][0][0] * d0[0] + G[rh][j][1][0] * d0[3];
            oy[rh] += G[rh][j][0][1] * d0[1] + G[rh][j][1][1] * d0[4];
            oz[rh] += G[rh][j][0][2] * d0[2] + G[rh][j][1][2] * d0[5];
        }
    }
    #pragma unroll
    for (int rh = 0; rh < 2; rh++) {
        ox[rh] += __shfl_xor_sync(0xffffffffu, ox[rh], 1);
        ox[rh] += __shfl_xor_sync(0xffffffffu, ox[rh], 2);
        oy[rh] += __shfl_xor_sync(0xffffffffu, oy[rh], 1);
        oy[rh] += __shfl_xor_sync(0xffffffffu, oy[rh], 2);
        oz[rh] += __shfl_xor_sync(0xffffffffu, oz[rh], 1);
        oz[rh] += __shfl_xor_sync(0xffffffffu, oz[rh], 2);
    }
    float* red = (float*)(sa + ARED);
    if (t4 == 0) {
        #pragma unroll
        for (int rh = 0; rh < 2; rh++) {
            const int row = g + 8 * rh;
            red[(row * 8 + band) * 3 + 0] = ox[rh];
            red[(row * 8 + band) * 3 + 1] = oy[rh];
            red[(row * 8 + band) * 3 + 2] = oz[rh];
        }
    }
    __syncthreads();
    if (tid < 48) {
        const int row = tid / 3, x = tid % 3;
        float s = 0.f;
        #pragma unroll
        for (int k = 0; k < 8; k++) s += red[(row * 8 + k) * 3 + x];
        out[((size_t)(b * SDIM) + s0 + row) * 3 + x] = s;
    }
}

// ---------------- launch ----------------
extern "C" void kernel_launch(void* const* d_in, const int* in_sizes, int n_in,
                              void* d_out, int out_size)
{
    const float* feats     = (const float*)d_in[0];
    const float* attn_bias = (const float*)d_in[1];
    const float* delta     = (const float*)d_in[2];
    const float* Wq  = (const float*)d_in[3];
    const float* bq  = (const float*)d_in[4];
    const float* Wk  = (const float*)d_in[5];
    const float* bk  = (const float*)d_in[6];
    const float* Wv  = (const float*)d_in[7];
    const float* bv  = (const float*)d_in[8];
    const float* Wfx = (const float*)d_in[9];
    const float* Wfy = (const float*)d_in[10];
    const float* Wfz = (const float*)d_in[11];
    float* out = (float*)d_out;

    prep_a_kernel<<<(ROWS * EDIM / 4) / 256, 256>>>(feats);
    prep_w_kernel<<<dim3(EDIM / 32, EDIM / 32, 3), 256>>>(Wq, Wk, Wv);

    cudaFuncSetAttribute(qkv_mma_kernel, cudaFuncAttributeMaxDynamicSharedMemorySize, GEMM_SMEM);
    dim3 gg(QKVN / 128, ROWS / 128);   // (18, 64)
    qkv_mma_kernel<<<gg, 256, GEMM_SMEM>>>(bq, bk, bv);

    vproj_kernel<<<ROWS / 8, 256>>>(Wfx, Wfy, Wfz);

    cudaFuncSetAttribute(attn_kernel, cudaFuncAttributeMaxDynamicSharedMemorySize, ATTN_SMEM);
    dim3 g2(SDIM / 16, BDIM);          // (16, 32)
    attn_kernel<<<g2, 256, ATTN_SMEM>>>(attn_bias, delta, out);
}

// round 14
// speedup vs baseline: 1.9877x; 1.0817x over previous
#include <cuda_runtime.h>
#include <cuda_fp16.h>
#include <cstdint>
#include <math.h>

#define BDIM 32
#define SDIM 256
#define EDIM 768
#define HDIM 32
#define DDIM 24
#define ROWS (BDIM*SDIM)     /* 8192 */
#define QKVN (3*EDIM)        /* 2304 */

// ---------------- device scratch (all fp16 path) ----------------
__device__ __align__(16) __half g_a_hi[(size_t)ROWS * EDIM];
__device__ __align__(16) __half g_b_hi[(size_t)QKVN * EDIM];   // wt[n][k]
// q/k attn-ready packed fp16: [b][h][s][32] (cols 24..31 stay zero)
__device__ __align__(16) __half g_qh[(size_t)ROWS * HDIM * 32];
__device__ __align__(16) __half g_kh[(size_t)ROWS * HDIM * 32];
__device__ float g_v [(size_t)ROWS * EDIM];
__device__ float g_vp[(size_t)ROWS * HDIM * 4];

// ---------------- PTX helpers (base sm_80+ ISA only) ----------------
__device__ __forceinline__ uint32_t smem_to_u32(const void* p) {
    uint32_t a;
    asm("{ .reg .u64 t; cvta.to.shared.u64 t, %1; cvt.u32.u64 %0, t; }" : "=r"(a) : "l"(p));
    return a;
}
__device__ __forceinline__ void cp_async16(uint32_t s, const void* g) {
    asm volatile("cp.async.cg.shared.global [%0], [%1], 16;" :: "r"(s), "l"(g) : "memory");
}
__device__ __forceinline__ void ldsm4(uint32_t* r, uint32_t addr) {
    asm volatile("ldmatrix.sync.aligned.m8n8.x4.shared.b16 {%0,%1,%2,%3}, [%4];"
                 : "=r"(r[0]), "=r"(r[1]), "=r"(r[2]), "=r"(r[3]) : "r"(addr));
}
__device__ __forceinline__ void mma16816(float* c, const uint32_t* a, const uint32_t* b) {
    asm volatile("mma.sync.aligned.m16n8k16.row.col.f32.f16.f16.f32 "
                 "{%0,%1,%2,%3}, {%4,%5,%6,%7}, {%8,%9}, {%0,%1,%2,%3};"
                 : "+f"(c[0]), "+f"(c[1]), "+f"(c[2]), "+f"(c[3])
                 : "r"(a[0]), "r"(a[1]), "r"(a[2]), "r"(a[3]), "r"(b[0]), "r"(b[1]));
}

// ---------------- prep: feats -> fp16 ----------------
__global__ __launch_bounds__(256) void prep_a_kernel(const float* __restrict__ feats)
{
    const size_t i = (size_t)blockIdx.x * 256 + threadIdx.x;
    float4 v = ((const float4*)feats)[i];
    __half2* ph = (__half2*)g_a_hi;
    ph[2*i]   = __floats2half2_rn(v.x, v.y);
    ph[2*i+1] = __floats2half2_rn(v.z, v.w);
}

// ---------------- prep: weights transpose -> fp16 ----------------
__global__ __launch_bounds__(256) void prep_w_kernel(
    const float* __restrict__ Wq, const float* __restrict__ Wk, const float* __restrict__ Wv)
{
    __shared__ float tile[32][33];
    const int which = blockIdx.z;
    const float* W = (which == 0) ? Wq : ((which == 1) ? Wk : Wv);
    const int n0 = blockIdx.x * 32, k0 = blockIdx.y * 32;
    const int tx = threadIdx.x & 31, ty = (threadIdx.x >> 5) * 4;
    #pragma unroll
    for (int i = 0; i < 4; i++)
        tile[ty + i][tx] = W[(size_t)(k0 + ty + i) * EDIM + n0 + tx];
    __syncthreads();
    #pragma unroll
    for (int i = 0; i < 4; i++) {
        const int n = n0 + ty + i, k = k0 + tx;
        g_b_hi[(size_t)(which * EDIM + n) * EDIM + k] = __float2half_rn(tile[tx][ty + i]);
    }
}

// ---------------- HMMA QKV GEMM: 128x128, 256 thr, 3-stage, single-pass fp16 ----------------
#define OFF_AHI 0
#define OFF_BHI 8192
#define STG 16384
#define GEMM_SMEM (3*STG)
#define NCHUNK (EDIM/32)

__device__ __forceinline__ uint32_t sw_addr(uint32_t tile, int row, int kc) {
    return tile + (row << 6) + ((kc ^ ((row >> 1) & 3)) << 4);
}

__global__ __launch_bounds__(256, 2) void qkv_mma_kernel(
    const float* __restrict__ bq, const float* __restrict__ bk, const float* __restrict__ bv)
{
    extern __shared__ char smem[];
    const uint32_t smem_base = smem_to_u32(smem);
    const int tid  = threadIdx.x;
    const int wid  = tid >> 5;
    const int lane = tid & 31;
    const int m0    = blockIdx.y * 128;
    const int nbase = blockIdx.x * 128;

    const int wm = wid & 1, wn = wid >> 1;
    const int mw = wm * 64, nw = wn * 32;
    const int lane7 = lane & 7, quad = lane >> 3;

    float c[4][4][4];
    #pragma unroll
    for (int i = 0; i < 4; i++)
        #pragma unroll
        for (int j = 0; j < 4; j++)
            #pragma unroll
            for (int r = 0; r < 4; r++) c[i][j][r] = 0.f;

    auto copy_stage = [&](int s) {
        const uint32_t sb = smem_base + (s % 3) * STG;
        const int k0 = s * 32;
        #pragma unroll
        for (int i = 0; i < 2; i++) {
            const int idx = tid + i * 256;
            const int row = idx >> 2, cc = idx & 3;
            const uint32_t soff = (row << 6) + ((cc ^ ((row >> 1) & 3)) << 4);
            const size_t ga = (size_t)(m0 + row) * EDIM + k0 + cc * 8;
            const size_t gb = (size_t)(nbase + row) * EDIM + k0 + cc * 8;
            cp_async16(sb + OFF_AHI + soff, g_a_hi + ga);
            cp_async16(sb + OFF_BHI + soff, g_b_hi + gb);
        }
        asm volatile("cp.async.commit_group;" ::: "memory");
    };

    copy_stage(0);
    copy_stage(1);

    for (int ch = 0; ch < NCHUNK; ch++) {
        if (ch + 1 < NCHUNK) {
            asm volatile("cp.async.wait_group 1;" ::: "memory");
        } else {
            asm volatile("cp.async.wait_group 0;" ::: "memory");
        }
        __syncthreads();
        if (ch + 2 < NCHUNK) copy_stage(ch + 2);

        const uint32_t sb = smem_base + (ch % 3) * STG;
        #pragma unroll
        for (int ks = 0; ks < 2; ks++) {
            uint32_t bh[4][2], a[4][4];
            #pragma unroll
            for (int j2 = 0; j2 < 2; j2++) {
                const int rowB = nw + j2 * 16 + ((quad >> 1) << 3) + lane7;
                const int kcB  = 2 * ks + (quad & 1);
                uint32_t r[4];
                ldsm4(r, sw_addr(sb + OFF_BHI, rowB, kcB));
                bh[2*j2][0] = r[0]; bh[2*j2][1] = r[1];
                bh[2*j2+1][0] = r[2]; bh[2*j2+1][1] = r[3];
            }
            const int rowA_ = ((quad & 1) << 3) + lane7;
            const int kcA   = 2 * ks + (quad >> 1);
            #pragma unroll
            for (int i = 0; i < 4; i++)
                ldsm4(a[i], sw_addr(sb + OFF_AHI, mw + 16 * i + rowA_, kcA));
            #pragma unroll
            for (int i = 0; i < 4; i++)
                #pragma unroll
                for (int j = 0; j < 4; j++)
                    mma16816(c[i][j], a[i], bh[j]);
        }
        __syncthreads();
    }

    // ---- epilogue ----
    const int which = blockIdx.x / 6;
    const int ncol_off = which * EDIM;
    const float* bias = (which == 0) ? bq : ((which == 1) ? bk : bv);
    const float scale = (which == 0) ? 0.20412414523193154f : 1.0f;
    const int g  = lane >> 2;
    const int t4 = lane & 3;

    #pragma unroll
    for (int i = 0; i < 4; i++) {
        #pragma unroll
        for (int half = 0; half < 2; half++) {
            const int row = m0 + mw + 16 * i + g + 8 * half;
            const int bb = row >> 8, tt = row & 255;
            #pragma unroll
            for (int j = 0; j < 4; j++) {
                const int col = nbase + nw + 8 * j + 2 * t4 - ncol_off;
                float2 v;
                v.x = (c[i][j][2*half + 0] + bias[col])     * scale;
                v.y = (c[i][j][2*half + 1] + bias[col + 1]) * scale;
                if (which == 2) {
                    *(float2*)&g_v[(size_t)row * EDIM + col] = v;
                } else {
                    const int h = col / DDIM, d = col - h * DDIM;
                    const size_t off = ((size_t)(bb * HDIM + h) * SDIM + tt) * 32 + d;
                    __half2 hv = __floats2half2_rn(v.x, v.y);
                    if (which == 0) {
                        *(__half2*)&g_qh[off] = hv;
                    } else {
                        *(__half2*)&g_kh[off] = hv;
                    }
                }
            }
        }
    }
}

// ---------------- vproj ----------------
__global__ __launch_bounds__(256) void vproj_kernel(
    const float* __restrict__ Wfx, const float* __restrict__ Wfy, const float* __restrict__ Wfz)
{
    const int row = blockIdx.x * 8 + (threadIdx.x >> 5);
    const int h   = threadIdx.x & 31;
    const float* v  = g_v + (size_t)row * EDIM + h * DDIM;
    const float* wx = Wfx + h * DDIM;
    const float* wy = Wfy + h * DDIM;
    const float* wz = Wfz + h * DDIM;
    float vx = 0.f, vy = 0.f, vz = 0.f;
    #pragma unroll
    for (int i = 0; i < 6; i++) {
        float4 vv = *(const float4*)(v  + 4 * i);
        float4 ax = *(const float4*)(wx + 4 * i);
        float4 ay = *(const float4*)(wy + 4 * i);
        float4 az = *(const float4*)(wz + 4 * i);
        vx += vv.x*ax.x + vv.y*ax.y + vv.z*ax.z + vv.w*ax.w;
        vy += vv.x*ay.x + vv.y*ay.y + vv.z*ay.z + vv.w*ay.w;
        vz += vv.x*az.x + vv.y*az.y + vv.z*az.z + vv.w*az.w;
    }
    const int b = row >> 8, t = row & 255;
    *(float4*)&g_vp[((size_t)(b * HDIM + h) * SDIM + t) * 4] = make_float4(vx, vy, vz, 0.f);
}

// ---------------- MMA attention: fp16, 2 MMAs/j, 16 s-rows, 2 blocks/SM ----------------
#define AKH   0
#define AVP   16384
#define ABIA  20480
#define BROW  1040
#define ASTG  37120     /* 20480 + 16*1040 = 37120 (128-aligned) */
#define AZP   (2*ASTG)
#define ARED  (2*ASTG + 1024)
#define ATTN_SMEM (2*ASTG + 1024 + 1536)

__global__ __launch_bounds__(256, 2) void attn_kernel(
    const float* __restrict__ attn_bias,
    const float* __restrict__ delta,
    float* __restrict__ out)
{
    extern __shared__ char sa[];
    const uint32_t sb = smem_to_u32(sa);
    const int b   = blockIdx.y;
    const int s0  = blockIdx.x * 16;
    const int tid = threadIdx.x;
    const int lane = tid & 31;
    const int band = tid >> 5;
    const int nb   = band * 32;
    const int g    = lane >> 2;
    const int t4   = lane & 3;
    const int l8   = lane & 7, l8h = lane >> 3;

    auto stage = [&](int hh) {
        const uint32_t bufs = sb + (hh & 1) * ASTG;
        const size_t kbase = (size_t)(b * HDIM + hh) * SDIM * 32;
        #pragma unroll
        for (int i = 0; i < 4; i++) {
            const int m = tid + i * 256;          // 0..1023 over 256 rows x 4 chunks
            const int r = m >> 2, c2 = m & 3;
            const uint32_t so = (r << 6) + ((c2 ^ ((r >> 1) & 3)) << 4);
            cp_async16(bufs + AKH + so, g_kh + kbase + r * 32 + c2 * 8);
        }
        cp_async16(bufs + AVP + tid * 16,
                   g_vp + (size_t)(b * HDIM + hh) * SDIM * 4 + tid * 4);
        const float* bsrc = attn_bias + (((size_t)b * HDIM + hh) * SDIM + s0) * SDIM;
        #pragma unroll
        for (int i = 0; i < 4; i++) {
            const int m = tid + i * 256;
            const int r = m >> 6, cc = m & 63;
            cp_async16(bufs + ABIA + r * BROW + cc * 16, bsrc + (size_t)r * SDIM + cc * 4);
        }
        asm volatile("cp.async.commit_group;" ::: "memory");
    };

    float G[2][4][2][3];
    #pragma unroll
    for (int r = 0; r < 2; r++)
        #pragma unroll
        for (int j = 0; j < 4; j++)
            #pragma unroll
            for (int cc = 0; cc < 2; cc++)
                #pragma unroll
                for (int x = 0; x < 3; x++) G[r][j][cc][x] = 0.f;

    stage(0);

    for (int h = 0; h < HDIM; h++) {
        const int par = h & 1;
        asm volatile("cp.async.wait_group 0;" ::: "memory");
        __syncthreads();
        if (h + 1 < HDIM) stage(h + 1);

        const size_t qoff = ((size_t)(b * HDIM + h) * SDIM + s0) * 32;
        const __half* qh = g_qh + qoff;
        uint32_t ah[2][4];
        #pragma unroll
        for (int kk = 0; kk < 2; kk++) {
            const int kb = 16 * kk + 2 * t4;
            ah[kk][0] = *(const uint32_t*)&qh[(g)     * 32 + kb];
            ah[kk][1] = *(const uint32_t*)&qh[(g + 8) * 32 + kb];
            ah[kk][2] = *(const uint32_t*)&qh[(g)     * 32 + kb + 8];
            ah[kk][3] = *(const uint32_t*)&qh[(g + 8) * 32 + kb + 8];
        }

        const uint32_t bufs = sb + par * ASTG;

        float c[4][4];
        #pragma unroll
        for (int j = 0; j < 4; j++)
            #pragma unroll
            for (int r = 0; r < 4; r++) c[j][r] = 0.f;

        #pragma unroll
        for (int j = 0; j < 4; j++) {
            uint32_t bh[4];
            const int rowB = nb + j * 8 + l8;
            const uint32_t so = (rowB << 6) + ((l8h ^ ((rowB >> 1) & 3)) << 4);
            ldsm4(bh, bufs + AKH + so);
            mma16816(c[j], ah[0], bh);
            mma16816(c[j], ah[1], bh + 2);
        }

        const char* bp0 = sa + par * ASTG + ABIA + g * BROW + (nb + 2 * t4) * 4;
        const char* bp1 = bp0 + 8 * BROW;
        float ps0 = 0.f, ps1 = 0.f;
        #pragma unroll
        for (int j = 0; j < 4; j++) {
            float2 b0 = *(const float2*)(bp0 + 32 * j);
            float2 b1 = *(const float2*)(bp1 + 32 * j);
            c[j][0] = __expf(c[j][0] + b0.x);
            c[j][1] = __expf(c[j][1] + b0.y);
            c[j][2] = __expf(c[j][2] + b1.x);
            c[j][3] = __expf(c[j][3] + b1.y);
            ps0 += c[j][0] + c[j][1];
            ps1 += c[j][2] + c[j][3];
        }
        ps0 += __shfl_xor_sync(0xffffffffu, ps0, 1);
        ps0 += __shfl_xor_sync(0xffffffffu, ps0, 2);
        ps1 += __shfl_xor_sync(0xffffffffu, ps1, 1);
        ps1 += __shfl_xor_sync(0xffffffffu, ps1, 2);
        float* zp = (float*)(sa + AZP + par * 512);
        if (t4 == 0) {
            zp[(g)     * 8 + band] = ps0;
            zp[(g + 8) * 8 + band] = ps1;
        }
        __syncthreads();

        float Z0, Z1;
        {
            float4 a0 = *(float4*)(zp + g * 8);
            float4 a1 = *(float4*)(zp + g * 8 + 4);
            Z0 = (a0.x + a0.y) + (a0.z + a0.w) + (a1.x + a1.y) + (a1.z + a1.w);
            float4 b0 = *(float4*)(zp + (g + 8) * 8);
            float4 b1 = *(float4*)(zp + (g + 8) * 8 + 4);
            Z1 = (b0.x + b0.y) + (b0.z + b0.w) + (b1.x + b1.y) + (b1.z + b1.w);
        }
        const float iz0 = __fdividef(1.f, Z0);
        const float iz1 = __fdividef(1.f, Z1);

        #pragma unroll
        for (int j = 0; j < 4; j++) {
            const char* vpp = sa + par * ASTG + AVP + (nb + 8 * j + 2 * t4) * 16;
            float4 v0 = *(const float4*)vpp;
            float4 v1 = *(const float4*)(vpp + 16);
            const float p00 = c[j][0] * iz0, p01 = c[j][1] * iz0;
            const float p10 = c[j][2] * iz1, p11 = c[j][3] * iz1;
            G[0][j][0][0] = fmaf(p00, v0.x, G[0][j][0][0]);
            G[0][j][0][1] = fmaf(p00, v0.y, G[0][j][0][1]);
            G[0][j][0][2] = fmaf(p00, v0.z, G[0][j][0][2]);
            G[0][j][1][0] = fmaf(p01, v1.x, G[0][j][1][0]);
            G[0][j][1][1] = fmaf(p01, v1.y, G[0][j][1][1]);
            G[0][j][1][2] = fmaf(p01, v1.z, G[0][j][1][2]);
            G[1][j][0][0] = fmaf(p10, v0.x, G[1][j][0][0]);
            G[1][j][0][1] = fmaf(p10, v0.y, G[1][j][0][1]);
            G[1][j][0][2] = fmaf(p10, v0.z, G[1][j][0][2]);
            G[1][j][1][0] = fmaf(p11, v1.x, G[1][j][1][0]);
            G[1][j][1][1] = fmaf(p11, v1.y, G[1][j][1][1]);
            G[1][j][1][2] = fmaf(p11, v1.z, G[1][j][1][2]);
        }
    }

    // ---- delta contraction + output ----
    float ox[2] = {0.f, 0.f}, oy[2] = {0.f, 0.f}, oz[2] = {0.f, 0.f};
    #pragma unroll
    for (int rh = 0; rh < 2; rh++) {
        const int srow = s0 + g + 8 * rh;
        const float* dp = delta + (size_t)(b * SDIM + srow) * SDIM * 3;
        #pragma unroll
        for (int j = 0; j < 4; j++) {
            const int t0 = nb + 8 * j + 2 * t4;
            const float* d0 = dp + t0 * 3;
            ox[rh] += G[rh][j][0][0] * d0[0] + G[rh][j][1][0] * d0[3];
            oy[rh] += G[rh][j][0][1] * d0[1] + G[rh][j][1][1] * d0[4];
            oz[rh] += G[rh][j][0][2] * d0[2] + G[rh][j][1][2] * d0[5];
        }
    }
    #pragma unroll
    for (int rh = 0; rh < 2; rh++) {
        ox[rh] += __shfl_xor_sync(0xffffffffu, ox[rh], 1);
        ox[rh] += __shfl_xor_sync(0xffffffffu, ox[rh], 2);
        oy[rh] += __shfl_xor_sync(0xffffffffu, oy[rh], 1);
        oy[rh] += __shfl_xor_sync(0xffffffffu, oy[rh], 2);
        oz[rh] += __shfl_xor_sync(0xffffffffu, oz[rh], 1);
        oz[rh] += __shfl_xor_sync(0xffffffffu, oz[rh], 2);
    }
    float* red = (float*)(sa + ARED);
    if (t4 == 0) {
        #pragma unroll
        for (int rh = 0; rh < 2; rh++) {
            const int row = g + 8 * rh;
            red[(row * 8 + band) * 3 + 0] = ox[rh];
            red[(row * 8 + band) * 3 + 1] = oy[rh];
            red[(row * 8 + band) * 3 + 2] = oz[rh];
        }
    }
    __syncthreads();
    if (tid < 48) {
        const int row = tid / 3, x = tid % 3;
        float s = 0.f;
        #pragma unroll
        for (int k = 0; k < 8; k++) s += red[(row * 8 + k) * 3 + x];
        out[((size_t)(b * SDIM) + s0 + row) * 3 + x] = s;
    }
}

// ---------------- launch ----------------
extern "C" void kernel_launch(void* const* d_in, const int* in_sizes, int n_in,
                              void* d_out, int out_size)
{
    const float* feats     = (const float*)d_in[0];
    const float* attn_bias = (const float*)d_in[1];
    const float* delta     = (const float*)d_in[2];
    const float* Wq  = (const float*)d_in[3];
    const float* bq  = (const float*)d_in[4];
    const float* Wk  = (const float*)d_in[5];
    const float* bk  = (const float*)d_in[6];
    const float* Wv  = (const float*)d_in[7];
    const float* bv  = (const float*)d_in[8];
    const float* Wfx = (const float*)d_in[9];
    const float* Wfy = (const float*)d_in[10];
    const float* Wfz = (const float*)d_in[11];
    float* out = (float*)d_out;

    prep_a_kernel<<<(ROWS * EDIM / 4) / 256, 256>>>(feats);
    prep_w_kernel<<<dim3(EDIM / 32, EDIM / 32, 3), 256>>>(Wq, Wk, Wv);

    cudaFuncSetAttribute(qkv_mma_kernel, cudaFuncAttributeMaxDynamicSharedMemorySize, GEMM_SMEM);
    dim3 gg(QKVN / 128, ROWS / 128);   // (18, 64)
    qkv_mma_kernel<<<gg, 256, GEMM_SMEM>>>(bq, bk, bv);

    vproj_kernel<<<ROWS / 8, 256>>>(Wfx, Wfy, Wfz);

    cudaFuncSetAttribute(attn_kernel, cudaFuncAttributeMaxDynamicSharedMemorySize, ATTN_SMEM);
    dim3 g2(SDIM / 16, BDIM);          // (16, 32)
    attn_kernel<<<g2, 256, ATTN_SMEM>>>(attn_bias, delta, out);
}